// round 3
// baseline (speedup 1.0000x reference)
#include <cuda_runtime.h>
#include <stdint.h>

#define NNODES 50000
#define NEDGES 800000
#define NPAIR  200000
#define DIN    256
#define H1DIM  512
#define H2DIM  256
#define H3DIM  160
#define NROWS_PAIR (2*NPAIR)

// ---------------- scratch (static device globals; no allocation) -------------
__device__ float g_deg_out[NNODES];
__device__ float g_deg_in[NNODES];
__device__ float g_onorm[NNODES];
__device__ float g_inorm[NNODES];
__device__ float g_bufA[(size_t)NNODES * 512];
__device__ float g_bufB[(size_t)NNODES * 512];
__device__ float g_bufC[(size_t)NNODES * 256];
__device__ float g_Z [(size_t)NROWS_PAIR * 160];
__device__ float g_M1[(size_t)NROWS_PAIR * 80];
__device__ float g_M2[(size_t)NROWS_PAIR * 40];

// ---------------- small kernels ----------------------------------------------
__global__ void deg_kernel(const int* __restrict__ src, const int* __restrict__ dst, int E)
{
    int i = blockIdx.x * blockDim.x + threadIdx.x;
    if (i < E) {
        atomicAdd(&g_deg_out[src[i]], 1.0f);
        atomicAdd(&g_deg_in [dst[i]], 1.0f);
    }
}

__global__ void norm_kernel(int n)
{
    int i = blockIdx.x * blockDim.x + threadIdx.x;
    if (i < n) {
        g_onorm[i] = rsqrtf(fmaxf(g_deg_out[i], 1.0f));
        g_inorm[i] = rsqrtf(fmaxf(g_deg_in [i], 1.0f));
    }
}

// one warp per edge; lane-strided over features (coalesced)
template<int D, bool USE_SRC_NORM>
__global__ void scatter_kernel(const float* __restrict__ feat,
                               const int* __restrict__ src,
                               const int* __restrict__ dst,
                               const float* __restrict__ w,
                               float* __restrict__ agg, int E)
{
    int warp = (blockIdx.x * blockDim.x + threadIdx.x) >> 5;
    int lane = threadIdx.x & 31;
    if (warp >= E) return;
    int s = src[warp], d = dst[warp];
    float scale = w[warp];
    if (USE_SRC_NORM) scale *= g_onorm[s];
    const float* fp = feat + (size_t)s * D;
    float*       ap = agg  + (size_t)d * D;
    #pragma unroll
    for (int f = lane; f < D; f += 32)
        atomicAdd(ap + f, fp[f] * scale);
}

// h3 = agg*in_norm + b3  -> write into output h-region
__global__ void finalize_h_kernel(const float* __restrict__ agg,
                                  const float* __restrict__ b3,
                                  float* __restrict__ outh, int total)
{
    int i = blockIdx.x * blockDim.x + threadIdx.x;
    if (i < total) {
        int row = i / H3DIM;
        int col = i - row * H3DIM;
        outh[i] = agg[i] * g_inorm[row] + b3[col];
    }
}

// Z[row] = h3[a] * h3[b] elementwise; rows 0..NPAIR-1 = pos, NPAIR.. = neg
__global__ void pairz_kernel(const float* __restrict__ h3,
                             const int* __restrict__ ps, const int* __restrict__ pd,
                             const int* __restrict__ ns, const int* __restrict__ nd)
{
    int i = blockIdx.x * blockDim.x + threadIdx.x;          // one float4 per thread
    int total = NROWS_PAIR * (H3DIM / 4);
    if (i >= total) return;
    int row = i / (H3DIM / 4);
    int c   = (i - row * (H3DIM / 4)) * 4;
    int a, b;
    if (row < NPAIR) { a = ps[row]; b = pd[row]; }
    else             { a = ns[row - NPAIR]; b = nd[row - NPAIR]; }
    float4 va = *(const float4*)(h3 + (size_t)a * H3DIM + c);
    float4 vb = *(const float4*)(h3 + (size_t)b * H3DIM + c);
    float4 r;
    r.x = va.x * vb.x; r.y = va.y * vb.y; r.z = va.z * vb.z; r.w = va.w * vb.w;
    *(float4*)(g_Z + (size_t)row * H3DIM + c) = r;
}

// final 40 -> 1 projection (no activation)
__global__ void gemv_kernel(const float* __restrict__ P3, const float* __restrict__ pb3,
                            float* __restrict__ out)
{
    int row = blockIdx.x * blockDim.x + threadIdx.x;
    if (row >= NROWS_PAIR) return;
    const float* hr = g_M2 + (size_t)row * 40;
    float acc = pb3[0];
    #pragma unroll
    for (int k = 0; k < 40; k++) acc += hr[k] * __ldg(&P3[k]);
    out[row] = acc;
}

// ---------------- generic fp32 tiled GEMM with fused pre/epilogue ------------
// C[M,Nn] = f_epi( f_pre(A)[M,K] @ B[K,Nn] )
// PRE: 0 raw, 1 A[m,k]*pre_out[m], 2 relu(A[m,k]*pre_in[m]+pre_bias[k])*pre_out[m]
// EROW: multiply C row by escale[m]
// ACT: 0 none, 1 relu, 2 leaky(0.2)
template<int PRE, int EROW, int ACT>
__global__ __launch_bounds__(256)
void gemm_kernel(const float* __restrict__ A, const float* __restrict__ B,
                 float* __restrict__ C, int M, int K, int Nn,
                 const float* __restrict__ pre_in, const float* __restrict__ pre_out,
                 const float* __restrict__ pre_bias,
                 const float* __restrict__ escale, const float* __restrict__ cbias)
{
    __shared__ float As[16][65];   // As[k][m], padded vs bank conflicts
    __shared__ float Bs[16][64];   // Bs[k][n]

    const int tid = threadIdx.x;
    const int tx = tid & 15;       // n quadrant
    const int ty = tid >> 4;       // m quadrant
    const int m0 = blockIdx.y * 64;
    const int n0 = blockIdx.x * 64;

    float acc[4][4];
    #pragma unroll
    for (int i = 0; i < 4; i++)
        #pragma unroll
        for (int j = 0; j < 4; j++) acc[i][j] = 0.0f;

    // A load map: r = tid/4 in [0,64), kk = (tid%4)*4
    const int ar = tid >> 2;
    const int akk = (tid & 3) * 4;
    // B load map: kr = tid/16 in [0,16), nc = (tid%16)*4
    const int bkr = tid >> 4;
    const int bnc = (tid & 15) * 4;

    for (int k0 = 0; k0 < K; k0 += 16) {
        // ---- load & transform A tile
        int gm = m0 + ar;
        float4 av = make_float4(0.f, 0.f, 0.f, 0.f);
        if (gm < M) {
            av = *(const float4*)(A + (size_t)gm * K + k0 + akk);
            if (PRE == 1) {
                float s = pre_out[gm];
                av.x *= s; av.y *= s; av.z *= s; av.w *= s;
            } else if (PRE == 2) {
                float si = pre_in[gm], so = pre_out[gm];
                av.x = fmaxf(av.x * si + pre_bias[k0 + akk + 0], 0.f) * so;
                av.y = fmaxf(av.y * si + pre_bias[k0 + akk + 1], 0.f) * so;
                av.z = fmaxf(av.z * si + pre_bias[k0 + akk + 2], 0.f) * so;
                av.w = fmaxf(av.w * si + pre_bias[k0 + akk + 3], 0.f) * so;
            }
        }
        As[akk + 0][ar] = av.x;
        As[akk + 1][ar] = av.y;
        As[akk + 2][ar] = av.z;
        As[akk + 3][ar] = av.w;

        // ---- load B tile (Nn always multiple of 4)
        float4 bv = make_float4(0.f, 0.f, 0.f, 0.f);
        if (n0 + bnc < Nn)
            bv = *(const float4*)(B + (size_t)(k0 + bkr) * Nn + n0 + bnc);
        *(float4*)&Bs[bkr][bnc] = bv;

        __syncthreads();

        #pragma unroll
        for (int k = 0; k < 16; k++) {
            float a0 = As[k][ty * 4 + 0];
            float a1 = As[k][ty * 4 + 1];
            float a2 = As[k][ty * 4 + 2];
            float a3 = As[k][ty * 4 + 3];
            float4 b4 = *(const float4*)&Bs[k][tx * 4];
            acc[0][0] += a0 * b4.x; acc[0][1] += a0 * b4.y; acc[0][2] += a0 * b4.z; acc[0][3] += a0 * b4.w;
            acc[1][0] += a1 * b4.x; acc[1][1] += a1 * b4.y; acc[1][2] += a1 * b4.z; acc[1][3] += a1 * b4.w;
            acc[2][0] += a2 * b4.x; acc[2][1] += a2 * b4.y; acc[2][2] += a2 * b4.z; acc[2][3] += a2 * b4.w;
            acc[3][0] += a3 * b4.x; acc[3][1] += a3 * b4.y; acc[3][2] += a3 * b4.z; acc[3][3] += a3 * b4.w;
        }
        __syncthreads();
    }

    // ---- epilogue
    #pragma unroll
    for (int i = 0; i < 4; i++) {
        int row = m0 + ty * 4 + i;
        if (row >= M) continue;
        float rs = EROW ? escale[row] : 1.0f;
        #pragma unroll
        for (int j = 0; j < 4; j++) {
            int col = n0 + tx * 4 + j;
            if (col >= Nn) continue;
            float c = acc[i][j];
            if (EROW) c *= rs;
            if (cbias) c += cbias[col];
            if (ACT == 1) c = fmaxf(c, 0.f);
            if (ACT == 2) c = (c > 0.f) ? c : 0.2f * c;
            C[(size_t)row * Nn + col] = c;
        }
    }
}

// ---------------- launch ------------------------------------------------------
static inline dim3 gemm_grid(int M, int Nn) { return dim3((Nn + 63) / 64, (M + 63) / 64); }

extern "C" void kernel_launch(void* const* d_in, const int* in_sizes, int n_in,
                              void* d_out, int out_size)
{
    const float* x   = (const float*)d_in[0];
    const float* w   = (const float*)d_in[1];
    const int* src   = (const int*)d_in[2];
    const int* dst   = (const int*)d_in[3];
    const int* psrc  = (const int*)d_in[4];
    const int* pdst  = (const int*)d_in[5];
    const int* nsrc  = (const int*)d_in[6];
    const int* ndst  = (const int*)d_in[7];
    const float* W1  = (const float*)d_in[8];
    const float* b1  = (const float*)d_in[9];
    const float* W2  = (const float*)d_in[10];
    const float* b2  = (const float*)d_in[11];
    const float* W3  = (const float*)d_in[12];
    const float* b3  = (const float*)d_in[13];
    const float* P1  = (const float*)d_in[14];
    const float* pb1 = (const float*)d_in[15];
    const float* P2  = (const float*)d_in[16];
    const float* pb2 = (const float*)d_in[17];
    const float* P3  = (const float*)d_in[18];
    const float* pb3 = (const float*)d_in[19];

    float* out = (float*)d_out;
    float* out_h = out + NROWS_PAIR;   // [NPAIR pos | NPAIR neg | N*160 h]

    // ALL device-symbol addresses must come from cudaGetSymbolAddress when
    // passed as kernel arguments from host code (host-side shadow symbols are
    // NOT device pointers — that was the R1 bug).
    void *p_degout, *p_degin, *p_onorm, *p_inorm;
    void *p_bufA, *p_bufB, *p_bufC, *p_Z, *p_M1, *p_M2;
    cudaGetSymbolAddress(&p_degout, g_deg_out);
    cudaGetSymbolAddress(&p_degin,  g_deg_in);
    cudaGetSymbolAddress(&p_onorm,  g_onorm);
    cudaGetSymbolAddress(&p_inorm,  g_inorm);
    cudaGetSymbolAddress(&p_bufA,   g_bufA);
    cudaGetSymbolAddress(&p_bufB,   g_bufB);
    cudaGetSymbolAddress(&p_bufC,   g_bufC);
    cudaGetSymbolAddress(&p_Z,      g_Z);
    cudaGetSymbolAddress(&p_M1,     g_M1);
    cudaGetSymbolAddress(&p_M2,     g_M2);
    float* onorm = (float*)p_onorm;
    float* inorm = (float*)p_inorm;
    float* bufA = (float*)p_bufA;
    float* bufB = (float*)p_bufB;
    float* bufC = (float*)p_bufC;
    float* Zb   = (float*)p_Z;
    float* M1b  = (float*)p_M1;
    float* M2b  = (float*)p_M2;

    const int E = NEDGES;

    // degrees + norms
    cudaMemsetAsync(p_degout, 0, NNODES * sizeof(float));
    cudaMemsetAsync(p_degin,  0, NNODES * sizeof(float));
    deg_kernel<<<(E + 255) / 256, 256>>>(src, dst, E);
    norm_kernel<<<(NNODES + 255) / 256, 256>>>(NNODES);

    const int scatter_blocks = (E * 32 + 255) / 256;

    // ---- layer 1: agg(x*onorm) -> @W1, *inorm+b1, relu
    cudaMemsetAsync(p_bufA, 0, (size_t)NNODES * DIN * sizeof(float));
    scatter_kernel<DIN, true><<<scatter_blocks, 256>>>(x, src, dst, w, bufA, E);
    gemm_kernel<0, 1, 1><<<gemm_grid(NNODES, H1DIM), 256>>>(
        bufA, W1, bufB, NNODES, DIN, H1DIM,
        nullptr, nullptr, nullptr, inorm, b1);

    // ---- layer 2: (h1*onorm)@W2 -> scatter -> (fused into layer-3 A-load)
    gemm_kernel<1, 0, 0><<<gemm_grid(NNODES, H2DIM), 256>>>(
        bufB, W2, bufA, NNODES, H1DIM, H2DIM,
        nullptr, onorm, nullptr, nullptr, nullptr);
    cudaMemsetAsync(p_bufC, 0, (size_t)NNODES * H2DIM * sizeof(float));
    scatter_kernel<H2DIM, false><<<scatter_blocks, 256>>>(bufA, src, dst, w, bufC, E);

    // ---- layer 3: A = relu(agg2*inorm+b2)*onorm ; @W3 -> scatter -> h3
    gemm_kernel<2, 0, 0><<<gemm_grid(NNODES, H3DIM), 256>>>(
        bufC, W3, bufB, NNODES, H2DIM, H3DIM,
        inorm, onorm, b2, nullptr, nullptr);
    cudaMemsetAsync(p_bufA, 0, (size_t)NNODES * H3DIM * sizeof(float));
    scatter_kernel<H3DIM, false><<<scatter_blocks, 256>>>(bufB, src, dst, w, bufA, E);
    finalize_h_kernel<<<(NNODES * H3DIM + 255) / 256, 256>>>(bufA, b3, out_h, NNODES * H3DIM);

    // ---- predictor on pos|neg pairs
    pairz_kernel<<<(NROWS_PAIR * (H3DIM / 4) + 255) / 256, 256>>>(out_h, psrc, pdst, nsrc, ndst);
    gemm_kernel<0, 0, 2><<<gemm_grid(NROWS_PAIR, 80), 256>>>(
        Zb, P1, M1b, NROWS_PAIR, H3DIM, 80,
        nullptr, nullptr, nullptr, nullptr, pb1);
    gemm_kernel<0, 0, 2><<<gemm_grid(NROWS_PAIR, 40), 256>>>(
        M1b, P2, M2b, NROWS_PAIR, 80, 40,
        nullptr, nullptr, nullptr, nullptr, pb2);
    gemv_kernel<<<(NROWS_PAIR + 255) / 256, 256>>>(P3, pb3, out);
}

// round 8
// speedup vs baseline: 1.7062x; 1.7062x over previous
#include <cuda_runtime.h>
#include <stdint.h>

#define NNODES 50000
#define NEDGES 800000
#define NPAIRS 200000
#define DIN    256
#define H1DIM  512
#define H2DIM  256
#define H3DIM  160
#define NROWS_PAIR (2*NPAIRS)

// ---------------- scratch (static device globals; no allocation) -------------
__device__ float g_deg_out[NNODES];
__device__ float g_deg_in[NNODES];
__device__ float g_onorm[NNODES];
__device__ float g_inorm[NNODES];
__device__ float g_bufA[(size_t)NNODES * 512];
__device__ float g_bufB[(size_t)NNODES * 512];
__device__ float g_bufC[(size_t)NNODES * 256];
__device__ float g_M1[(size_t)NROWS_PAIR * 80];
__device__ float g_M2[(size_t)NROWS_PAIR * 40];
// transposed (and tf32-rounded) weights
__device__ float g_Wt[512*256 + 256*512 + 160*256 + 80*160 + 40*80];

// ---------------- helpers -----------------------------------------------------
static __device__ __forceinline__ float tf32r(float x) {
    uint32_t t;
    asm("cvt.rna.tf32.f32 %0, %1;" : "=r"(t) : "f"(x));
    return __uint_as_float(t);
}

// ---------------- small kernels ----------------------------------------------
__global__ void deg_kernel(const int* __restrict__ src, const int* __restrict__ dst, int E)
{
    int i = blockIdx.x * blockDim.x + threadIdx.x;
    if (i < E) {
        atomicAdd(&g_deg_out[src[i]], 1.0f);
        atomicAdd(&g_deg_in [dst[i]], 1.0f);
    }
}

__global__ void norm_kernel(int n)
{
    int i = blockIdx.x * blockDim.x + threadIdx.x;
    if (i < n) {
        g_onorm[i] = rsqrtf(fmaxf(g_deg_out[i], 1.0f));
        g_inorm[i] = rsqrtf(fmaxf(g_deg_in [i], 1.0f));
    }
}

// transpose + round weights to tf32 (so B smem loads need no cvt)
__global__ void transpose_kernel(const float* __restrict__ W, float* __restrict__ Wt, int K, int N)
{
    int i = blockIdx.x * blockDim.x + threadIdx.x;
    if (i < K * N) {
        int k = i / N, n = i - k * N;
        Wt[n * K + k] = tf32r(W[i]);
    }
}

// one warp per edge; lane-strided over features (coalesced)
template<int D, bool USE_SRC_NORM>
__global__ void scatter_kernel(const float* __restrict__ feat,
                               const int* __restrict__ src,
                               const int* __restrict__ dst,
                               const float* __restrict__ w,
                               float* __restrict__ agg, int E)
{
    int warp = (blockIdx.x * blockDim.x + threadIdx.x) >> 5;
    int lane = threadIdx.x & 31;
    if (warp >= E) return;
    int s = src[warp], d = dst[warp];
    float scale = w[warp];
    if (USE_SRC_NORM) scale *= g_onorm[s];
    const float* fp = feat + (size_t)s * D;
    float*       ap = agg  + (size_t)d * D;
    #pragma unroll
    for (int f = lane; f < D; f += 32)
        atomicAdd(ap + f, fp[f] * scale);
}

__global__ void finalize_h_kernel(const float* __restrict__ agg,
                                  const float* __restrict__ b3,
                                  float* __restrict__ outh, int total)
{
    int i = blockIdx.x * blockDim.x + threadIdx.x;
    if (i < total) {
        int row = i / H3DIM;
        int col = i - row * H3DIM;
        outh[i] = agg[i] * g_inorm[row] + b3[col];
    }
}

__global__ void gemv_kernel(const float* __restrict__ P3, const float* __restrict__ pb3,
                            float* __restrict__ out)
{
    int row = blockIdx.x * blockDim.x + threadIdx.x;
    if (row >= NROWS_PAIR) return;
    const float* hr = g_M2 + (size_t)row * 40;
    float acc = pb3[0];
    #pragma unroll
    for (int k = 0; k < 40; k++) acc += hr[k] * __ldg(&P3[k]);
    out[row] = acc;
}

// ---------------- tf32 mma.sync GEMM ------------------------------------------
// C[M,Nn] = epi( pre(A)[M,K] @ Bt[Nn,K]^T )
// PRE: 0 raw, 2 relu(A*pre_in[m]+pre_bias[k]), 3 pair-gather A[ia]*A[ib]
// EROW: C row *= escale[m].  ACT: 0 none, 1 relu, 2 leaky(0.2)
// Tile: 128m x 128n per CTA, 8 warps of 64m x 32n, K-chunk 32, double buffer.
// smem rows padded to 36 floats -> fragment loads are bank-conflict-free.
#define SROW 36
#define SBUF (128 * SROW)                   // floats per tile buffer
#define MM_SMEM_BYTES (4 * SBUF * 4)        // A0 A1 B0 B1

template<int PRE, int EROW, int ACT>
__global__ __launch_bounds__(256)
void mm_gemm(const float* __restrict__ A, const float* __restrict__ Bt,
             float* __restrict__ C, int M, int K, int Nn,
             const float* __restrict__ pre_in, const float* __restrict__ pre_bias,
             const float* __restrict__ escale, const float* __restrict__ cbias,
             const int* __restrict__ ips, const int* __restrict__ ipd,
             const int* __restrict__ ins, const int* __restrict__ ind)
{
    extern __shared__ float smem[];
    float* sA = smem;               // [2][128][SROW]
    float* sB = smem + 2 * SBUF;    // [2][128][SROW]

    const int tid = threadIdx.x;
    const int m0 = blockIdx.y * 128;
    const int n0 = blockIdx.x * 128;
    const int lane = tid & 31;
    const int wq = tid >> 5;
    const int wm = wq & 1;          // 0..1  (64-row slab)
    const int wn = wq >> 1;         // 0..3  (32-col slab)
    const int lr = lane >> 2;       // 0..7
    const int lc = lane & 3;        // 0..3

    const int nch = (K + 31) / 32;

    float acc[4][4][4];
    #pragma unroll
    for (int mt = 0; mt < 4; mt++)
        #pragma unroll
        for (int nt = 0; nt < 4; nt++)
            #pragma unroll
            for (int r = 0; r < 4; r++) acc[mt][nt][r] = 0.0f;

    // --- global fetch of chunk c into registers (8 float4) -------------------
    float4 rgA[4], rgB[4];
    auto fetch = [&](int c) {
        const int k0 = c * 32;
        #pragma unroll
        for (int i = 0; i < 4; i++) {
            int idx = i * 256 + tid;          // 0..1023
            int r   = idx >> 3;               // 0..127
            int kk  = (idx & 7) * 4;
            int gk  = k0 + kk;
            // A
            float4 v = make_float4(0.f, 0.f, 0.f, 0.f);
            int gm = m0 + r;
            if (gm < M && gk < K) {
                if (PRE == 3) {
                    int ia, ib;
                    if (gm < NPAIRS) { ia = ips[gm]; ib = ipd[gm]; }
                    else             { ia = ins[gm - NPAIRS]; ib = ind[gm - NPAIRS]; }
                    float4 va = *(const float4*)(A + (size_t)ia * K + gk);
                    float4 vb = *(const float4*)(A + (size_t)ib * K + gk);
                    v.x = va.x * vb.x; v.y = va.y * vb.y; v.z = va.z * vb.z; v.w = va.w * vb.w;
                } else {
                    v = *(const float4*)(A + (size_t)gm * K + gk);
                    if (PRE == 2) {
                        float si = pre_in[gm];
                        float4 bb = *(const float4*)(pre_bias + gk);
                        v.x = fmaxf(v.x * si + bb.x, 0.f);
                        v.y = fmaxf(v.y * si + bb.y, 0.f);
                        v.z = fmaxf(v.z * si + bb.z, 0.f);
                        v.w = fmaxf(v.w * si + bb.w, 0.f);
                    }
                }
            }
            rgA[i] = v;
            // B (already tf32-rounded)
            float4 u = make_float4(0.f, 0.f, 0.f, 0.f);
            int gn = n0 + r;
            if (gn < Nn && gk < K)
                u = *(const float4*)(Bt + (size_t)gn * K + gk);
            rgB[i] = u;
        }
    };
    // --- store staged registers into smem buffer b ---------------------------
    auto store_stage = [&](int b) {
        float* dA = sA + b * SBUF;
        float* dB = sB + b * SBUF;
        #pragma unroll
        for (int i = 0; i < 4; i++) {
            int idx = i * 256 + tid;
            int r   = idx >> 3;
            int kk  = (idx & 7) * 4;
            float4 v = rgA[i];
            v.x = tf32r(v.x); v.y = tf32r(v.y); v.z = tf32r(v.z); v.w = tf32r(v.w);
            *(float4*)(dA + r * SROW + kk) = v;
            *(float4*)(dB + r * SROW + kk) = rgB[i];
        }
    };
    // --- mma over smem buffer b ----------------------------------------------
    auto compute = [&](int b) {
        const float* cA = sA + b * SBUF;
        const float* cB = sB + b * SBUF;
        #pragma unroll
        for (int ks = 0; ks < 4; ks++) {
            const int kb = ks * 8;
            uint32_t af[4][4], bf[4][2];
            #pragma unroll
            for (int mt = 0; mt < 4; mt++) {
                int r0 = wm * 64 + mt * 16 + lr;
                af[mt][0] = __float_as_uint(cA[ r0      * SROW + kb + lc]);
                af[mt][1] = __float_as_uint(cA[(r0 + 8) * SROW + kb + lc]);
                af[mt][2] = __float_as_uint(cA[ r0      * SROW + kb + 4 + lc]);
                af[mt][3] = __float_as_uint(cA[(r0 + 8) * SROW + kb + 4 + lc]);
            }
            #pragma unroll
            for (int nt = 0; nt < 4; nt++) {
                int c0 = wn * 32 + nt * 8 + lr;
                bf[nt][0] = __float_as_uint(cB[c0 * SROW + kb + lc]);
                bf[nt][1] = __float_as_uint(cB[c0 * SROW + kb + 4 + lc]);
            }
            #pragma unroll
            for (int mt = 0; mt < 4; mt++)
                #pragma unroll
                for (int nt = 0; nt < 4; nt++)
                    asm volatile(
                        "mma.sync.aligned.m16n8k8.row.col.f32.tf32.tf32.f32 "
                        "{%0,%1,%2,%3}, {%4,%5,%6,%7}, {%8,%9}, {%0,%1,%2,%3};"
                        : "+f"(acc[mt][nt][0]), "+f"(acc[mt][nt][1]),
                          "+f"(acc[mt][nt][2]), "+f"(acc[mt][nt][3])
                        : "r"(af[mt][0]), "r"(af[mt][1]), "r"(af[mt][2]), "r"(af[mt][3]),
                          "r"(bf[nt][0]), "r"(bf[nt][1]));
        }
    };

    // --- pipelined mainloop ---------------------------------------------------
    fetch(0);
    store_stage(0);
    for (int c = 0; c < nch; c++) {
        __syncthreads();                 // buf c&1 staged & prior compute done
        if (c + 1 < nch) fetch(c + 1);   // LDGs in flight during compute
        compute(c & 1);
        if (c + 1 < nch) store_stage((c + 1) & 1);
    }

    // --- epilogue -------------------------------------------------------------
    #pragma unroll
    for (int mt = 0; mt < 4; mt++) {
        int r0 = m0 + wm * 64 + mt * 16 + lr;
        int r1 = r0 + 8;
        float s0 = 1.f, s1 = 1.f;
        if (EROW) {
            if (r0 < M) s0 = escale[r0];
            if (r1 < M) s1 = escale[r1];
        }
        #pragma unroll
        for (int nt = 0; nt < 4; nt++) {
            int col = n0 + wn * 32 + nt * 8 + lc * 2;
            if (col >= Nn) continue;     // Nn multiple of 8 -> col+1 < Nn too
            float bx = 0.f, by = 0.f;
            if (cbias) { bx = cbias[col]; by = cbias[col + 1]; }
            #pragma unroll
            for (int half = 0; half < 2; half++) {
                int row = half ? r1 : r0;
                if (row >= M) continue;
                float sc = half ? s1 : s0;
                float vx = acc[mt][nt][half * 2 + 0] * sc + bx;
                float vy = acc[mt][nt][half * 2 + 1] * sc + by;
                if (ACT == 1) { vx = fmaxf(vx, 0.f); vy = fmaxf(vy, 0.f); }
                else if (ACT == 2) {
                    vx = (vx > 0.f) ? vx : 0.2f * vx;
                    vy = (vy > 0.f) ? vy : 0.2f * vy;
                }
                *(float2*)(C + (size_t)row * Nn + col) = make_float2(vx, vy);
            }
        }
    }
}

// ---------------- launch ------------------------------------------------------
static inline dim3 mm_grid(int M, int Nn) { return dim3((Nn + 127) / 128, (M + 127) / 128); }

extern "C" void kernel_launch(void* const* d_in, const int* in_sizes, int n_in,
                              void* d_out, int out_size)
{
    const float* x   = (const float*)d_in[0];
    const float* w   = (const float*)d_in[1];
    const int* src   = (const int*)d_in[2];
    const int* dst   = (const int*)d_in[3];
    const int* psrc  = (const int*)d_in[4];
    const int* pdst  = (const int*)d_in[5];
    const int* nsrc  = (const int*)d_in[6];
    const int* ndst  = (const int*)d_in[7];
    const float* W1  = (const float*)d_in[8];
    const float* b1  = (const float*)d_in[9];
    const float* W2  = (const float*)d_in[10];
    const float* b2  = (const float*)d_in[11];
    const float* W3  = (const float*)d_in[12];
    const float* b3  = (const float*)d_in[13];
    const float* P1  = (const float*)d_in[14];
    const float* pb1 = (const float*)d_in[15];
    const float* P2  = (const float*)d_in[16];
    const float* pb2 = (const float*)d_in[17];
    const float* P3  = (const float*)d_in[18];
    const float* pb3 = (const float*)d_in[19];

    float* out = (float*)d_out;
    float* out_h = out + NROWS_PAIR;   // [NPAIR pos | NPAIR neg | N*160 h]

    void *p_degout, *p_degin, *p_onorm, *p_inorm;
    void *p_bufA, *p_bufB, *p_bufC, *p_M1, *p_M2, *p_Wt;
    cudaGetSymbolAddress(&p_degout, g_deg_out);
    cudaGetSymbolAddress(&p_degin,  g_deg_in);
    cudaGetSymbolAddress(&p_onorm,  g_onorm);
    cudaGetSymbolAddress(&p_inorm,  g_inorm);
    cudaGetSymbolAddress(&p_bufA,   g_bufA);
    cudaGetSymbolAddress(&p_bufB,   g_bufB);
    cudaGetSymbolAddress(&p_bufC,   g_bufC);
    cudaGetSymbolAddress(&p_M1,     g_M1);
    cudaGetSymbolAddress(&p_M2,     g_M2);
    cudaGetSymbolAddress(&p_Wt,     g_Wt);
    float* onorm = (float*)p_onorm;
    float* inorm = (float*)p_inorm;
    float* bufA = (float*)p_bufA;
    float* bufB = (float*)p_bufB;
    float* bufC = (float*)p_bufC;
    float* M1b  = (float*)p_M1;
    float* M2b  = (float*)p_M2;
    float* W1t = (float*)p_Wt;
    float* W2t = W1t + 512 * 256;
    float* W3t = W2t + 256 * 512;
    float* P1t = W3t + 160 * 256;
    float* P2t = P1t + 80 * 160;

    cudaFuncSetAttribute(mm_gemm<0,1,1>, cudaFuncAttributeMaxDynamicSharedMemorySize, MM_SMEM_BYTES);
    cudaFuncSetAttribute(mm_gemm<0,1,0>, cudaFuncAttributeMaxDynamicSharedMemorySize, MM_SMEM_BYTES);
    cudaFuncSetAttribute(mm_gemm<2,1,0>, cudaFuncAttributeMaxDynamicSharedMemorySize, MM_SMEM_BYTES);
    cudaFuncSetAttribute(mm_gemm<3,0,2>, cudaFuncAttributeMaxDynamicSharedMemorySize, MM_SMEM_BYTES);
    cudaFuncSetAttribute(mm_gemm<0,0,2>, cudaFuncAttributeMaxDynamicSharedMemorySize, MM_SMEM_BYTES);

    const int E = NEDGES;

    // degrees + norms + weight transposes (tf32-rounded)
    cudaMemsetAsync(p_degout, 0, NNODES * sizeof(float));
    cudaMemsetAsync(p_degin,  0, NNODES * sizeof(float));
    deg_kernel<<<(E + 255) / 256, 256>>>(src, dst, E);
    norm_kernel<<<(NNODES + 255) / 256, 256>>>(NNODES);
    transpose_kernel<<<(256*512 + 255) / 256, 256>>>(W1, W1t, 256, 512);
    transpose_kernel<<<(512*256 + 255) / 256, 256>>>(W2, W2t, 512, 256);
    transpose_kernel<<<(256*160 + 255) / 256, 256>>>(W3, W3t, 256, 160);
    transpose_kernel<<<(160*80  + 255) / 256, 256>>>(P1, P1t, 160, 80);
    transpose_kernel<<<(80*40   + 255) / 256, 256>>>(P2, P2t, 80, 40);

    const int scatter_blocks = (E * 32 + 255) / 256;

    // ---- layer 1: agg(x*onorm) -> @W1, *inorm + b1, relu
    cudaMemsetAsync(p_bufA, 0, (size_t)NNODES * DIN * sizeof(float));
    scatter_kernel<DIN, true><<<scatter_blocks, 256>>>(x, src, dst, w, bufA, E);
    mm_gemm<0,1,1><<<mm_grid(NNODES, H1DIM), 256, MM_SMEM_BYTES>>>(
        bufA, W1t, bufB, NNODES, DIN, H1DIM,
        nullptr, nullptr, inorm, b1, nullptr, nullptr, nullptr, nullptr);

    // ---- layer 2: h1@W2 with epilogue row-scale by onorm (commutes) -> scatter
    mm_gemm<0,1,0><<<mm_grid(NNODES, H2DIM), 256, MM_SMEM_BYTES>>>(
        bufB, W2t, bufA, NNODES, H1DIM, H2DIM,
        nullptr, nullptr, onorm, nullptr, nullptr, nullptr, nullptr, nullptr);
    cudaMemsetAsync(p_bufC, 0, (size_t)NNODES * H2DIM * sizeof(float));
    scatter_kernel<H2DIM, false><<<scatter_blocks, 256>>>(bufA, src, dst, w, bufC, E);

    // ---- layer 3: A = relu(agg2*inorm + b2); @W3; epilogue *onorm -> scatter -> h3
    mm_gemm<2,1,0><<<mm_grid(NNODES, H3DIM), 256, MM_SMEM_BYTES>>>(
        bufC, W3t, bufB, NNODES, H2DIM, H3DIM,
        inorm, b2, onorm, nullptr, nullptr, nullptr, nullptr, nullptr);
    cudaMemsetAsync(p_bufA, 0, (size_t)NNODES * H3DIM * sizeof(float));
    scatter_kernel<H3DIM, false><<<scatter_blocks, 256>>>(bufB, src, dst, w, bufA, E);
    finalize_h_kernel<<<(NNODES * H3DIM + 255) / 256, 256>>>(bufA, b3, out_h, NNODES * H3DIM);

    // ---- predictor: fused pair-gather GEMM (160->80, leaky), 80->40 leaky, 40->1
    mm_gemm<3,0,2><<<mm_grid(NROWS_PAIR, 80), 256, MM_SMEM_BYTES>>>(
        out_h, P1t, M1b, NROWS_PAIR, H3DIM, 80,
        nullptr, nullptr, nullptr, pb1, psrc, pdst, nsrc, ndst);
    mm_gemm<0,0,2><<<mm_grid(NROWS_PAIR, 40), 256, MM_SMEM_BYTES>>>(
        M1b, P2t, M2b, NROWS_PAIR, 80, 40,
        nullptr, nullptr, nullptr, pb2, nullptr, nullptr, nullptr, nullptr);
    gemv_kernel<<<(NROWS_PAIR + 255) / 256, 256>>>(P3, pb3, out);
}

// round 9
// speedup vs baseline: 2.0258x; 1.1873x over previous
#include <cuda_runtime.h>
#include <stdint.h>

#define NNODES 50000
#define NEDGES 800000
#define NPAIRS 200000
#define DIN    256
#define H1DIM  512
#define H2DIM  256
#define H3DIM  160
#define NROWS_PAIR (2*NPAIRS)

// ---------------- scratch (static device globals; no allocation) -------------
__device__ int   g_cnt_out[NNODES];
__device__ int   g_cnt_in[NNODES];
__device__ float g_onorm[NNODES];
__device__ float g_inorm[NNODES];
__device__ int   g_rowptr[NNODES + 1];
__device__ int   g_cursor[NNODES];
__device__ int   g_csr_src[NEDGES];
__device__ float g_csr_w[NEDGES];
__device__ float g_bufA[(size_t)NNODES * 512];
__device__ float g_bufB[(size_t)NNODES * 512];
__device__ float g_bufC[(size_t)NNODES * 256];
__device__ float g_M1[(size_t)NROWS_PAIR * 80];
__device__ float g_M2[(size_t)NROWS_PAIR * 40];
// transposed (and tf32-rounded) weights
__device__ float g_Wt[512*256 + 256*512 + 160*256 + 80*160 + 40*80];

// ---------------- helpers -----------------------------------------------------
static __device__ __forceinline__ float tf32r(float x) {
    uint32_t t;
    asm("cvt.rna.tf32.f32 %0, %1;" : "=r"(t) : "f"(x));
    return __uint_as_float(t);
}

// ---------------- graph preprocessing ----------------------------------------
__global__ void count_kernel(const int* __restrict__ src, const int* __restrict__ dst, int E)
{
    int i = blockIdx.x * blockDim.x + threadIdx.x;
    if (i < E) {
        atomicAdd(&g_cnt_out[src[i]], 1);
        atomicAdd(&g_cnt_in [dst[i]], 1);
    }
}

__global__ void norm_kernel(int n)
{
    int i = blockIdx.x * blockDim.x + threadIdx.x;
    if (i < n) {
        g_onorm[i] = rsqrtf(fmaxf((float)g_cnt_out[i], 1.0f));
        g_inorm[i] = rsqrtf(fmaxf((float)g_cnt_in [i], 1.0f));
    }
}

// single-block exclusive scan of g_cnt_in -> g_rowptr (+ cursor copy)
__global__ void scan_kernel()
{
    __shared__ int sbuf[2][1024];
    __shared__ int carry;
    const int tid = threadIdx.x;
    if (tid == 0) carry = 0;
    __syncthreads();
    for (int base = 0; base < NNODES; base += 1024) {
        int v = (base + tid < NNODES) ? g_cnt_in[base + tid] : 0;
        int pi = 0;
        sbuf[0][tid] = v;
        __syncthreads();
        #pragma unroll
        for (int off = 1; off < 1024; off <<= 1) {
            int s = sbuf[pi][tid];
            if (tid >= off) s += sbuf[pi][tid - off];
            sbuf[pi ^ 1][tid] = s;
            pi ^= 1;
            __syncthreads();
        }
        int incl = sbuf[pi][tid];
        int excl = incl - v + carry;
        if (base + tid < NNODES) {
            g_rowptr[base + tid] = excl;
            g_cursor[base + tid] = excl;
        }
        __syncthreads();
        if (tid == 1023) carry += incl;
        __syncthreads();
    }
    if (tid == 0) g_rowptr[NNODES] = carry;
}

// fill CSR (by dst). csr_w = w_e * onorm[src_e] makes all layers uniform.
__global__ void fill_kernel(const int* __restrict__ src, const int* __restrict__ dst,
                            const float* __restrict__ w, int E)
{
    int i = blockIdx.x * blockDim.x + threadIdx.x;
    if (i < E) {
        int s = src[i];
        int slot = atomicAdd(&g_cursor[dst[i]], 1);
        g_csr_src[slot] = s;
        g_csr_w[slot]   = w[i] * g_onorm[s];
    }
}

// ---------------- CSR aggregation: agg[d] = sum_e wn_e * feat[src_e] ---------
// one warp per dst node; edge meta loaded 32-wide then shfl-broadcast
template<int D>
__global__ void csr_agg_kernel(const float* __restrict__ feat, float* __restrict__ agg)
{
    const int node = (blockIdx.x * blockDim.x + threadIdx.x) >> 5;
    const int lane = threadIdx.x & 31;
    if (node >= NNODES) return;
    const int beg = g_rowptr[node], end = g_rowptr[node + 1];

    constexpr int NV = D / 4;              // float4 per row (64 or 40)
    float4 acc0 = make_float4(0.f, 0.f, 0.f, 0.f);
    float4 acc1 = make_float4(0.f, 0.f, 0.f, 0.f);
    const bool has2 = (NV > 32) && (lane + 32 < NV);

    for (int base = beg; base < end; base += 32) {
        int cnt = min(32, end - base);
        int   sl = (lane < cnt) ? g_csr_src[base + lane] : 0;
        float wl = (lane < cnt) ? g_csr_w [base + lane] : 0.f;
        for (int j = 0; j < cnt; j++) {
            int   s  = __shfl_sync(0xFFFFFFFFu, sl, j);
            float wv = __shfl_sync(0xFFFFFFFFu, wl, j);
            const float4* row = (const float4*)(feat + (size_t)s * D);
            float4 a = row[lane];
            acc0.x += wv * a.x; acc0.y += wv * a.y;
            acc0.z += wv * a.z; acc0.w += wv * a.w;
            if (has2) {
                float4 b = row[lane + 32];
                acc1.x += wv * b.x; acc1.y += wv * b.y;
                acc1.z += wv * b.z; acc1.w += wv * b.w;
            }
        }
    }
    float4* orow = (float4*)(agg + (size_t)node * D);
    if (lane < NV) orow[lane] = acc0;
    if (has2) orow[lane + 32] = acc1;
}

// ---------------- small kernels ----------------------------------------------
__global__ void transpose_kernel(const float* __restrict__ W, float* __restrict__ Wt, int K, int N)
{
    int i = blockIdx.x * blockDim.x + threadIdx.x;
    if (i < K * N) {
        int k = i / N, n = i - k * N;
        Wt[n * K + k] = tf32r(W[i]);
    }
}

__global__ void finalize_h_kernel(const float* __restrict__ agg,
                                  const float* __restrict__ b3,
                                  float* __restrict__ outh, int total)
{
    int i = blockIdx.x * blockDim.x + threadIdx.x;
    if (i < total) {
        int row = i / H3DIM;
        int col = i - row * H3DIM;
        outh[i] = agg[i] * g_inorm[row] + b3[col];
    }
}

__global__ void gemv_kernel(const float* __restrict__ P3, const float* __restrict__ pb3,
                            float* __restrict__ out)
{
    int row = blockIdx.x * blockDim.x + threadIdx.x;
    if (row >= NROWS_PAIR) return;
    const float* hr = g_M2 + (size_t)row * 40;
    float acc = pb3[0];
    #pragma unroll
    for (int k = 0; k < 40; k++) acc += hr[k] * __ldg(&P3[k]);
    out[row] = acc;
}

// ---------------- tf32 mma.sync GEMM ------------------------------------------
// C[M,Nn] = epi( pre(A)[M,K] @ Bt[Nn,K]^T )
// PRE: 0 raw, 2 relu(A*pre_in[m]+pre_bias[k]), 3 pair-gather A[ia]*A[ib]
// EROW: C row *= escale[m].  ACT: 0 none, 1 relu, 2 leaky(0.2)
#define SROW 36
#define SBUF (128 * SROW)
#define MM_SMEM_BYTES (4 * SBUF * 4)

template<int PRE, int EROW, int ACT>
__global__ __launch_bounds__(256)
void mm_gemm(const float* __restrict__ A, const float* __restrict__ Bt,
             float* __restrict__ C, int M, int K, int Nn,
             const float* __restrict__ pre_in, const float* __restrict__ pre_bias,
             const float* __restrict__ escale, const float* __restrict__ cbias,
             const int* __restrict__ ips, const int* __restrict__ ipd,
             const int* __restrict__ ins, const int* __restrict__ ind)
{
    extern __shared__ float smem[];
    float* sA = smem;
    float* sB = smem + 2 * SBUF;

    const int tid = threadIdx.x;
    const int m0 = blockIdx.y * 128;
    const int n0 = blockIdx.x * 128;
    const int lane = tid & 31;
    const int wq = tid >> 5;
    const int wm = wq & 1;
    const int wn = wq >> 1;
    const int lr = lane >> 2;
    const int lc = lane & 3;

    const int nch = (K + 31) / 32;

    float acc[4][4][4];
    #pragma unroll
    for (int mt = 0; mt < 4; mt++)
        #pragma unroll
        for (int nt = 0; nt < 4; nt++)
            #pragma unroll
            for (int r = 0; r < 4; r++) acc[mt][nt][r] = 0.0f;

    float4 rgA[4], rgB[4];
    auto fetch = [&](int c) {
        const int k0 = c * 32;
        #pragma unroll
        for (int i = 0; i < 4; i++) {
            int idx = i * 256 + tid;
            int r   = idx >> 3;
            int kk  = (idx & 7) * 4;
            int gk  = k0 + kk;
            float4 v = make_float4(0.f, 0.f, 0.f, 0.f);
            int gm = m0 + r;
            if (gm < M && gk < K) {
                if (PRE == 3) {
                    int ia, ib;
                    if (gm < NPAIRS) { ia = ips[gm]; ib = ipd[gm]; }
                    else             { ia = ins[gm - NPAIRS]; ib = ind[gm - NPAIRS]; }
                    float4 va = *(const float4*)(A + (size_t)ia * K + gk);
                    float4 vb = *(const float4*)(A + (size_t)ib * K + gk);
                    v.x = va.x * vb.x; v.y = va.y * vb.y; v.z = va.z * vb.z; v.w = va.w * vb.w;
                } else {
                    v = *(const float4*)(A + (size_t)gm * K + gk);
                    if (PRE == 2) {
                        float si = pre_in[gm];
                        float4 bb = *(const float4*)(pre_bias + gk);
                        v.x = fmaxf(v.x * si + bb.x, 0.f);
                        v.y = fmaxf(v.y * si + bb.y, 0.f);
                        v.z = fmaxf(v.z * si + bb.z, 0.f);
                        v.w = fmaxf(v.w * si + bb.w, 0.f);
                    }
                }
            }
            rgA[i] = v;
            float4 u = make_float4(0.f, 0.f, 0.f, 0.f);
            int gn = n0 + r;
            if (gn < Nn && gk < K)
                u = *(const float4*)(Bt + (size_t)gn * K + gk);
            rgB[i] = u;
        }
    };
    auto store_stage = [&](int b) {
        float* dA = sA + b * SBUF;
        float* dB = sB + b * SBUF;
        #pragma unroll
        for (int i = 0; i < 4; i++) {
            int idx = i * 256 + tid;
            int r   = idx >> 3;
            int kk  = (idx & 7) * 4;
            float4 v = rgA[i];
            v.x = tf32r(v.x); v.y = tf32r(v.y); v.z = tf32r(v.z); v.w = tf32r(v.w);
            *(float4*)(dA + r * SROW + kk) = v;
            *(float4*)(dB + r * SROW + kk) = rgB[i];
        }
    };
    auto compute = [&](int b) {
        const float* cA = sA + b * SBUF;
        const float* cB = sB + b * SBUF;
        #pragma unroll
        for (int ks = 0; ks < 4; ks++) {
            const int kb = ks * 8;
            uint32_t af[4][4], bf[4][2];
            #pragma unroll
            for (int mt = 0; mt < 4; mt++) {
                int r0 = wm * 64 + mt * 16 + lr;
                af[mt][0] = __float_as_uint(cA[ r0      * SROW + kb + lc]);
                af[mt][1] = __float_as_uint(cA[(r0 + 8) * SROW + kb + lc]);
                af[mt][2] = __float_as_uint(cA[ r0      * SROW + kb + 4 + lc]);
                af[mt][3] = __float_as_uint(cA[(r0 + 8) * SROW + kb + 4 + lc]);
            }
            #pragma unroll
            for (int nt = 0; nt < 4; nt++) {
                int c0 = wn * 32 + nt * 8 + lr;
                bf[nt][0] = __float_as_uint(cB[c0 * SROW + kb + lc]);
                bf[nt][1] = __float_as_uint(cB[c0 * SROW + kb + 4 + lc]);
            }
            #pragma unroll
            for (int mt = 0; mt < 4; mt++)
                #pragma unroll
                for (int nt = 0; nt < 4; nt++)
                    asm volatile(
                        "mma.sync.aligned.m16n8k8.row.col.f32.tf32.tf32.f32 "
                        "{%0,%1,%2,%3}, {%4,%5,%6,%7}, {%8,%9}, {%0,%1,%2,%3};"
                        : "+f"(acc[mt][nt][0]), "+f"(acc[mt][nt][1]),
                          "+f"(acc[mt][nt][2]), "+f"(acc[mt][nt][3])
                        : "r"(af[mt][0]), "r"(af[mt][1]), "r"(af[mt][2]), "r"(af[mt][3]),
                          "r"(bf[nt][0]), "r"(bf[nt][1]));
        }
    };

    fetch(0);
    store_stage(0);
    for (int c = 0; c < nch; c++) {
        __syncthreads();
        if (c + 1 < nch) fetch(c + 1);
        compute(c & 1);
        if (c + 1 < nch) store_stage((c + 1) & 1);
    }

    #pragma unroll
    for (int mt = 0; mt < 4; mt++) {
        int r0 = m0 + wm * 64 + mt * 16 + lr;
        int r1 = r0 + 8;
        float s0 = 1.f, s1 = 1.f;
        if (EROW) {
            if (r0 < M) s0 = escale[r0];
            if (r1 < M) s1 = escale[r1];
        }
        #pragma unroll
        for (int nt = 0; nt < 4; nt++) {
            int col = n0 + wn * 32 + nt * 8 + lc * 2;
            if (col >= Nn) continue;
            float bx = 0.f, by = 0.f;
            if (cbias) { bx = cbias[col]; by = cbias[col + 1]; }
            #pragma unroll
            for (int half = 0; half < 2; half++) {
                int row = half ? r1 : r0;
                if (row >= M) continue;
                float sc = half ? s1 : s0;
                float vx = acc[mt][nt][half * 2 + 0] * sc + bx;
                float vy = acc[mt][nt][half * 2 + 1] * sc + by;
                if (ACT == 1) { vx = fmaxf(vx, 0.f); vy = fmaxf(vy, 0.f); }
                else if (ACT == 2) {
                    vx = (vx > 0.f) ? vx : 0.2f * vx;
                    vy = (vy > 0.f) ? vy : 0.2f * vy;
                }
                *(float2*)(C + (size_t)row * Nn + col) = make_float2(vx, vy);
            }
        }
    }
}

// ---------------- launch ------------------------------------------------------
static inline dim3 mm_grid(int M, int Nn) { return dim3((Nn + 127) / 128, (M + 127) / 128); }

extern "C" void kernel_launch(void* const* d_in, const int* in_sizes, int n_in,
                              void* d_out, int out_size)
{
    const float* x   = (const float*)d_in[0];
    const float* w   = (const float*)d_in[1];
    const int* src   = (const int*)d_in[2];
    const int* dst   = (const int*)d_in[3];
    const int* psrc  = (const int*)d_in[4];
    const int* pdst  = (const int*)d_in[5];
    const int* nsrc  = (const int*)d_in[6];
    const int* ndst  = (const int*)d_in[7];
    const float* W1  = (const float*)d_in[8];
    const float* b1  = (const float*)d_in[9];
    const float* W2  = (const float*)d_in[10];
    const float* b2  = (const float*)d_in[11];
    const float* W3  = (const float*)d_in[12];
    const float* b3  = (const float*)d_in[13];
    const float* P1  = (const float*)d_in[14];
    const float* pb1 = (const float*)d_in[15];
    const float* P2  = (const float*)d_in[16];
    const float* pb2 = (const float*)d_in[17];
    const float* P3  = (const float*)d_in[18];
    const float* pb3 = (const float*)d_in[19];

    float* out = (float*)d_out;
    float* out_h = out + NROWS_PAIR;   // [NPAIR pos | NPAIR neg | N*160 h]

    void *p_cntout, *p_cntin, *p_inorm;
    void *p_bufA, *p_bufB, *p_bufC, *p_M1, *p_M2, *p_Wt;
    cudaGetSymbolAddress(&p_cntout, g_cnt_out);
    cudaGetSymbolAddress(&p_cntin,  g_cnt_in);
    cudaGetSymbolAddress(&p_inorm,  g_inorm);
    cudaGetSymbolAddress(&p_bufA,   g_bufA);
    cudaGetSymbolAddress(&p_bufB,   g_bufB);
    cudaGetSymbolAddress(&p_bufC,   g_bufC);
    cudaGetSymbolAddress(&p_M1,     g_M1);
    cudaGetSymbolAddress(&p_M2,     g_M2);
    cudaGetSymbolAddress(&p_Wt,     g_Wt);
    float* inorm = (float*)p_inorm;
    float* bufA = (float*)p_bufA;
    float* bufB = (float*)p_bufB;
    float* bufC = (float*)p_bufC;
    float* M1b  = (float*)p_M1;
    float* M2b  = (float*)p_M2;
    float* W1t = (float*)p_Wt;
    float* W2t = W1t + 512 * 256;
    float* W3t = W2t + 256 * 512;
    float* P1t = W3t + 160 * 256;
    float* P2t = P1t + 80 * 160;

    cudaFuncSetAttribute(mm_gemm<0,1,1>, cudaFuncAttributeMaxDynamicSharedMemorySize, MM_SMEM_BYTES);
    cudaFuncSetAttribute(mm_gemm<0,0,0>, cudaFuncAttributeMaxDynamicSharedMemorySize, MM_SMEM_BYTES);
    cudaFuncSetAttribute(mm_gemm<2,0,0>, cudaFuncAttributeMaxDynamicSharedMemorySize, MM_SMEM_BYTES);
    cudaFuncSetAttribute(mm_gemm<3,0,2>, cudaFuncAttributeMaxDynamicSharedMemorySize, MM_SMEM_BYTES);
    cudaFuncSetAttribute(mm_gemm<0,0,2>, cudaFuncAttributeMaxDynamicSharedMemorySize, MM_SMEM_BYTES);

    const int E = NEDGES;

    // ---- graph preprocessing: counts -> norms -> CSR
    cudaMemsetAsync(p_cntout, 0, NNODES * sizeof(int));
    cudaMemsetAsync(p_cntin,  0, NNODES * sizeof(int));
    count_kernel<<<(E + 255) / 256, 256>>>(src, dst, E);
    norm_kernel<<<(NNODES + 255) / 256, 256>>>(NNODES);
    scan_kernel<<<1, 1024>>>();
    fill_kernel<<<(E + 255) / 256, 256>>>(src, dst, w, E);

    // weight transposes (tf32-rounded) — independent, overlap-friendly
    transpose_kernel<<<(256*512 + 255) / 256, 256>>>(W1, W1t, 256, 512);
    transpose_kernel<<<(512*256 + 255) / 256, 256>>>(W2, W2t, 512, 256);
    transpose_kernel<<<(256*160 + 255) / 256, 256>>>(W3, W3t, 256, 160);
    transpose_kernel<<<(160*80  + 255) / 256, 256>>>(P1, P1t, 160, 80);
    transpose_kernel<<<(80*40   + 255) / 256, 256>>>(P2, P2t, 80, 40);

    const int agg_blocks = (NNODES * 32 + 255) / 256;

    // ---- layer 1: agg(x) -> @W1 *inorm + b1, relu
    csr_agg_kernel<DIN><<<agg_blocks, 256>>>(x, bufA);
    mm_gemm<0,1,1><<<mm_grid(NNODES, H1DIM), 256, MM_SMEM_BYTES>>>(
        bufA, W1t, bufB, NNODES, DIN, H1DIM,
        nullptr, nullptr, inorm, b1, nullptr, nullptr, nullptr, nullptr);

    // ---- layer 2: h1@W2 -> agg (onorm lives in csr_w)
    mm_gemm<0,0,0><<<mm_grid(NNODES, H2DIM), 256, MM_SMEM_BYTES>>>(
        bufB, W2t, bufA, NNODES, H1DIM, H2DIM,
        nullptr, nullptr, nullptr, nullptr, nullptr, nullptr, nullptr, nullptr);
    csr_agg_kernel<H2DIM><<<agg_blocks, 256>>>(bufA, bufC);

    // ---- layer 3: A = relu(agg2*inorm + b2); @W3 -> agg -> *inorm + b3 -> h3
    mm_gemm<2,0,0><<<mm_grid(NNODES, H3DIM), 256, MM_SMEM_BYTES>>>(
        bufC, W3t, bufB, NNODES, H2DIM, H3DIM,
        inorm, b2, nullptr, nullptr, nullptr, nullptr, nullptr, nullptr);
    csr_agg_kernel<H3DIM><<<agg_blocks, 256>>>(bufB, bufA);
    finalize_h_kernel<<<(NNODES * H3DIM + 255) / 256, 256>>>(bufA, b3, out_h, NNODES * H3DIM);

    // ---- predictor: fused pair-gather GEMM (160->80 leaky), 80->40 leaky, 40->1
    mm_gemm<3,0,2><<<mm_grid(NROWS_PAIR, 80), 256, MM_SMEM_BYTES>>>(
        out_h, P1t, M1b, NROWS_PAIR, H3DIM, 80,
        nullptr, nullptr, nullptr, pb1, psrc, pdst, nsrc, ndst);
    mm_gemm<0,0,2><<<mm_grid(NROWS_PAIR, 40), 256, MM_SMEM_BYTES>>>(
        M1b, P2t, M2b, NROWS_PAIR, 80, 40,
        nullptr, nullptr, nullptr, pb2, nullptr, nullptr, nullptr, nullptr);
    gemv_kernel<<<(NROWS_PAIR + 255) / 256, 256>>>(P3, pb3, out);
}

// round 10
// speedup vs baseline: 2.2186x; 1.0952x over previous
#include <cuda_runtime.h>
#include <stdint.h>

#define NNODES 50000
#define NEDGES 800000
#define NPAIRS 200000
#define DIN    256
#define H1DIM  512
#define H2DIM  256
#define H3DIM  160
#define NROWS_PAIR (2*NPAIRS)

// ---------------- scratch (static device globals; no allocation) -------------
__device__ int   g_cnt_out[NNODES];
__device__ int   g_cnt_in[NNODES];
__device__ float g_onorm[NNODES];
__device__ float g_inorm[NNODES];
__device__ int   g_rowptr[NNODES + 1];
__device__ int   g_cursor[NNODES];
__device__ int   g_csr_src[NEDGES];
__device__ float g_csr_w[NEDGES];
__device__ float g_bufA[(size_t)NNODES * 512];
__device__ float g_bufB[(size_t)NNODES * 512];
__device__ float g_bufC[(size_t)NNODES * 256];
__device__ float g_M1[(size_t)NROWS_PAIR * 80];
__device__ float g_M2[(size_t)NROWS_PAIR * 40];
__device__ float g_Wt[512*256 + 256*512 + 160*256 + 80*160 + 40*80];

// ---------------- helpers -----------------------------------------------------
static __device__ __forceinline__ float tf32r(float x) {
    uint32_t t;
    asm("cvt.rna.tf32.f32 %0, %1;" : "=r"(t) : "f"(x));
    return __uint_as_float(t);
}
static __device__ __forceinline__ uint32_t smem_u32(const void* p) {
    uint32_t a;
    asm("{ .reg .u64 t; cvta.to.shared.u64 t, %1; cvt.u32.u64 %0, t; }" : "=r"(a) : "l"(p));
    return a;
}

// ---------------- graph preprocessing ----------------------------------------
__global__ void count_kernel(const int* __restrict__ src, const int* __restrict__ dst, int E)
{
    int i = blockIdx.x * blockDim.x + threadIdx.x;
    if (i < E) {
        atomicAdd(&g_cnt_out[src[i]], 1);
        atomicAdd(&g_cnt_in [dst[i]], 1);
    }
}

__global__ void norm_kernel(int n)
{
    int i = blockIdx.x * blockDim.x + threadIdx.x;
    if (i < n) {
        g_onorm[i] = rsqrtf(fmaxf((float)g_cnt_out[i], 1.0f));
        g_inorm[i] = rsqrtf(fmaxf((float)g_cnt_in [i], 1.0f));
    }
}

__global__ void scan_kernel()
{
    __shared__ int sbuf[2][1024];
    __shared__ int carry;
    const int tid = threadIdx.x;
    if (tid == 0) carry = 0;
    __syncthreads();
    for (int base = 0; base < NNODES; base += 1024) {
        int v = (base + tid < NNODES) ? g_cnt_in[base + tid] : 0;
        int pi = 0;
        sbuf[0][tid] = v;
        __syncthreads();
        #pragma unroll
        for (int off = 1; off < 1024; off <<= 1) {
            int s = sbuf[pi][tid];
            if (tid >= off) s += sbuf[pi][tid - off];
            sbuf[pi ^ 1][tid] = s;
            pi ^= 1;
            __syncthreads();
        }
        int incl = sbuf[pi][tid];
        int excl = incl - v + carry;
        if (base + tid < NNODES) {
            g_rowptr[base + tid] = excl;
            g_cursor[base + tid] = excl;
        }
        __syncthreads();
        if (tid == 1023) carry += incl;
        __syncthreads();
    }
    if (tid == 0) g_rowptr[NNODES] = carry;
}

__global__ void fill_kernel(const int* __restrict__ src, const int* __restrict__ dst,
                            const float* __restrict__ w, int E)
{
    int i = blockIdx.x * blockDim.x + threadIdx.x;
    if (i < E) {
        int s = src[i];
        int slot = atomicAdd(&g_cursor[dst[i]], 1);
        g_csr_src[slot] = s;
        g_csr_w[slot]   = w[i] * g_onorm[s];
    }
}

// ---------------- CSR aggregation with fused epilogues ------------------------
// EPI: 0 = tf32-round(acc)           (feeds GEMM A directly)
//      1 = tf32-round(relu(acc*inorm + bias))
//      2 = acc*inorm + bias          (fp32 output, e.g. out_h)
template<int D, int EPI>
__global__ void csr_agg_kernel(const float* __restrict__ feat, float* __restrict__ outp,
                               const float* __restrict__ bias)
{
    const int node = (blockIdx.x * blockDim.x + threadIdx.x) >> 5;
    const int lane = threadIdx.x & 31;
    if (node >= NNODES) return;
    const int beg = g_rowptr[node], end = g_rowptr[node + 1];

    constexpr int NV = D / 4;
    constexpr bool HAS2 = (NV > 32);
    float4 acc0 = make_float4(0.f, 0.f, 0.f, 0.f);
    float4 acc1 = make_float4(0.f, 0.f, 0.f, 0.f);
    const bool use2 = HAS2 && (lane + 32 < NV);

    for (int base = beg; base < end; base += 32) {
        int cnt = min(32, end - base);
        int   sl = (lane < cnt) ? g_csr_src[base + lane] : 0;
        float wl = (lane < cnt) ? g_csr_w [base + lane] : 0.f;
        int j = 0;
        for (; j + 4 <= cnt; j += 4) {
            int   s0 = __shfl_sync(0xFFFFFFFFu, sl, j + 0);
            int   s1 = __shfl_sync(0xFFFFFFFFu, sl, j + 1);
            int   s2 = __shfl_sync(0xFFFFFFFFu, sl, j + 2);
            int   s3 = __shfl_sync(0xFFFFFFFFu, sl, j + 3);
            float w0 = __shfl_sync(0xFFFFFFFFu, wl, j + 0);
            float w1 = __shfl_sync(0xFFFFFFFFu, wl, j + 1);
            float w2 = __shfl_sync(0xFFFFFFFFu, wl, j + 2);
            float w3 = __shfl_sync(0xFFFFFFFFu, wl, j + 3);
            const float4* r0 = (const float4*)(feat + (size_t)s0 * D);
            const float4* r1 = (const float4*)(feat + (size_t)s1 * D);
            const float4* r2 = (const float4*)(feat + (size_t)s2 * D);
            const float4* r3 = (const float4*)(feat + (size_t)s3 * D);
            if (lane < NV) {
                float4 a0 = r0[lane], a1 = r1[lane], a2 = r2[lane], a3 = r3[lane];
                acc0.x += w0*a0.x + w1*a1.x + w2*a2.x + w3*a3.x;
                acc0.y += w0*a0.y + w1*a1.y + w2*a2.y + w3*a3.y;
                acc0.z += w0*a0.z + w1*a1.z + w2*a2.z + w3*a3.z;
                acc0.w += w0*a0.w + w1*a1.w + w2*a2.w + w3*a3.w;
            }
            if (use2) {
                float4 b0 = r0[lane+32], b1 = r1[lane+32], b2 = r2[lane+32], b3 = r3[lane+32];
                acc1.x += w0*b0.x + w1*b1.x + w2*b2.x + w3*b3.x;
                acc1.y += w0*b0.y + w1*b1.y + w2*b2.y + w3*b3.y;
                acc1.z += w0*b0.z + w1*b1.z + w2*b2.z + w3*b3.z;
                acc1.w += w0*b0.w + w1*b1.w + w2*b2.w + w3*b3.w;
            }
        }
        for (; j < cnt; j++) {
            int   s  = __shfl_sync(0xFFFFFFFFu, sl, j);
            float wv = __shfl_sync(0xFFFFFFFFu, wl, j);
            const float4* row = (const float4*)(feat + (size_t)s * D);
            if (lane < NV) {
                float4 a = row[lane];
                acc0.x += wv*a.x; acc0.y += wv*a.y; acc0.z += wv*a.z; acc0.w += wv*a.w;
            }
            if (use2) {
                float4 b = row[lane+32];
                acc1.x += wv*b.x; acc1.y += wv*b.y; acc1.z += wv*b.z; acc1.w += wv*b.w;
            }
        }
    }

    float nin = (EPI >= 1) ? g_inorm[node] : 1.0f;
    float4* orow = (float4*)(outp + (size_t)node * D);
    if (lane < NV) {
        float4 v = acc0;
        if (EPI >= 1) {
            float4 bb = *(const float4*)(bias + lane * 4);
            v.x = v.x * nin + bb.x; v.y = v.y * nin + bb.y;
            v.z = v.z * nin + bb.z; v.w = v.w * nin + bb.w;
            if (EPI == 1) {
                v.x = fmaxf(v.x, 0.f); v.y = fmaxf(v.y, 0.f);
                v.z = fmaxf(v.z, 0.f); v.w = fmaxf(v.w, 0.f);
            }
        }
        if (EPI != 2) { v.x = tf32r(v.x); v.y = tf32r(v.y); v.z = tf32r(v.z); v.w = tf32r(v.w); }
        orow[lane] = v;
    }
    if (use2) {
        float4 v = acc1;
        if (EPI >= 1) {
            float4 bb = *(const float4*)(bias + (lane + 32) * 4);
            v.x = v.x * nin + bb.x; v.y = v.y * nin + bb.y;
            v.z = v.z * nin + bb.z; v.w = v.w * nin + bb.w;
            if (EPI == 1) {
                v.x = fmaxf(v.x, 0.f); v.y = fmaxf(v.y, 0.f);
                v.z = fmaxf(v.z, 0.f); v.w = fmaxf(v.w, 0.f);
            }
        }
        if (EPI != 2) { v.x = tf32r(v.x); v.y = tf32r(v.y); v.z = tf32r(v.z); v.w = tf32r(v.w); }
        orow[lane + 32] = v;
    }
}

// ---------------- small kernels ----------------------------------------------
__global__ void transpose_kernel(const float* __restrict__ W, float* __restrict__ Wt, int K, int N)
{
    int i = blockIdx.x * blockDim.x + threadIdx.x;
    if (i < K * N) {
        int k = i / N, n = i - k * N;
        Wt[n * K + k] = tf32r(W[i]);
    }
}

__global__ void gemv_kernel(const float* __restrict__ P3, const float* __restrict__ pb3,
                            float* __restrict__ out)
{
    int row = blockIdx.x * blockDim.x + threadIdx.x;
    if (row >= NROWS_PAIR) return;
    const float* hr = g_M2 + (size_t)row * 40;
    float acc = pb3[0];
    #pragma unroll
    for (int k = 0; k < 40; k++) acc += hr[k] * __ldg(&P3[k]);
    out[row] = acc;
}

// ---------------- tf32 mma.sync GEMM (4 warps, 64x64 warp tiles) -------------
// C[M,Nn] = epi( pre(A)[M,K] @ Bt[Nn,K]^T )
// PRE: 0 raw (A already tf32; cp.async staging), 3 pair-gather A[ia]*A[ib] (reg path)
// EROW: C row *= escale[m].  ACT: 0 none, 1 relu, 2 leaky(0.2). ROUND: tf32-round C.
#define SROW 36
#define SBUF (128 * SROW)
#define MM_SMEM_BYTES (4 * SBUF * 4)

template<int PRE, int EROW, int ACT, int ROUND>
__global__ __launch_bounds__(128)
void mm_gemm(const float* __restrict__ A, const float* __restrict__ Bt,
             float* __restrict__ C, int M, int K, int Nn,
             const float* __restrict__ escale, const float* __restrict__ cbias,
             const int* __restrict__ ips, const int* __restrict__ ipd,
             const int* __restrict__ ins, const int* __restrict__ ind)
{
    extern __shared__ float smem[];
    float* sA = smem;               // [2][SBUF]
    float* sB = smem + 2 * SBUF;    // [2][SBUF]
    const uint32_t sAu = smem_u32(sA);
    const uint32_t sBu = smem_u32(sB);

    const int tid  = threadIdx.x;
    const int m0   = blockIdx.y * 128;
    const int n0   = blockIdx.x * 128;
    const int lane = tid & 31;
    const int wq   = tid >> 5;
    const int wm   = wq & 1;        // 64-row slab
    const int wn   = wq >> 1;       // 64-col slab
    const int lr   = lane >> 2;
    const int lc   = lane & 3;
    const int sub  = lane >> 3;
    const int rr   = lane & 7;
    const int nch  = (K + 31) / 32;

    float acc[4][8][4];
    #pragma unroll
    for (int mt = 0; mt < 4; mt++)
        #pragma unroll
        for (int nt = 0; nt < 8; nt++)
            #pragma unroll
            for (int r = 0; r < 4; r++) acc[mt][nt][r] = 0.0f;

    // ---- cp.async staging of chunk c (A skipped when PRE==3) ---------------
    auto issue = [&](int c) {
        const int b = c & 1, k0 = c * 32;
        #pragma unroll
        for (int i = 0; i < 8; i++) {
            int idx = i * 128 + tid;
            int r = idx >> 3, kk = (idx & 7) * 4, gk = k0 + kk;
            uint32_t so = (uint32_t)(r * SROW + kk) * 4 + (uint32_t)b * (SBUF * 4);
            int gkc = min(gk, K - 4);
            if (PRE != 3) {
                int gm = m0 + r;
                int sz = ((gm < M) && (gk < K)) ? 16 : 0;
                const float* ga = A + (size_t)min(gm, M - 1) * K + gkc;
                asm volatile("cp.async.ca.shared.global [%0], [%1], 16, %2;"
                             :: "r"(sAu + so), "l"(ga), "r"(sz));
            }
            int gn = n0 + r;
            int szb = ((gn < Nn) && (gk < K)) ? 16 : 0;
            const float* gb = Bt + (size_t)min(gn, Nn - 1) * K + gkc;
            asm volatile("cp.async.ca.shared.global [%0], [%1], 16, %2;"
                         :: "r"(sBu + so), "l"(gb), "r"(szb));
        }
        asm volatile("cp.async.commit_group;" ::: "memory");
    };

    // ---- PRE==3: register staging of A (pair product) ----------------------
    float4 rgA[8];
    auto fetchA = [&](int c) {
        const int k0 = c * 32;
        #pragma unroll
        for (int i = 0; i < 8; i++) {
            int idx = i * 128 + tid;
            int r = idx >> 3, kk = (idx & 7) * 4, gk = k0 + kk;
            float4 v = make_float4(0.f, 0.f, 0.f, 0.f);
            int gm = m0 + r;
            if (gm < M && gk < K) {
                int ia, ib;
                if (gm < NPAIRS) { ia = ips[gm]; ib = ipd[gm]; }
                else             { ia = ins[gm - NPAIRS]; ib = ind[gm - NPAIRS]; }
                float4 va = *(const float4*)(A + (size_t)ia * K + gk);
                float4 vb = *(const float4*)(A + (size_t)ib * K + gk);
                v.x = va.x * vb.x; v.y = va.y * vb.y; v.z = va.z * vb.z; v.w = va.w * vb.w;
            }
            rgA[i] = v;
        }
    };
    auto storeA = [&](int b) {
        #pragma unroll
        for (int i = 0; i < 8; i++) {
            int idx = i * 128 + tid;
            int r = idx >> 3, kk = (idx & 7) * 4;
            float4 v = rgA[i];
            v.x = tf32r(v.x); v.y = tf32r(v.y); v.z = tf32r(v.z); v.w = tf32r(v.w);
            *(float4*)(sA + b * SBUF + r * SROW + kk) = v;
        }
    };

    // ---- compute over staged chunk buffer b --------------------------------
    auto compute = [&](int b) {
        const uint32_t baseA = sAu + (uint32_t)b * (SBUF * 4);
        const uint32_t baseB = sBu + (uint32_t)b * (SBUF * 4);
        #pragma unroll
        for (int ks = 0; ks < 4; ks++) {
            const int kb = ks * 8;
            uint32_t af[4][4], bf[8][2];
            #pragma unroll
            for (int mt = 0; mt < 4; mt++) {
                int row = wm * 64 + mt * 16 + rr + (sub & 1) * 8;
                int col = kb + (sub >> 1) * 4;
                uint32_t ad = baseA + (uint32_t)(row * SROW + col) * 4;
                asm volatile("ldmatrix.sync.aligned.m8n8.x4.shared.b16 {%0,%1,%2,%3}, [%4];"
                             : "=r"(af[mt][0]), "=r"(af[mt][1]), "=r"(af[mt][2]), "=r"(af[mt][3])
                             : "r"(ad));
            }
            #pragma unroll
            for (int ntp = 0; ntp < 4; ntp++) {
                int row = wn * 64 + ntp * 16 + rr + (sub >> 1) * 8;
                int col = kb + (sub & 1) * 4;
                uint32_t bd = baseB + (uint32_t)(row * SROW + col) * 4;
                asm volatile("ldmatrix.sync.aligned.m8n8.x4.shared.b16 {%0,%1,%2,%3}, [%4];"
                             : "=r"(bf[2*ntp][0]), "=r"(bf[2*ntp][1]),
                               "=r"(bf[2*ntp+1][0]), "=r"(bf[2*ntp+1][1])
                             : "r"(bd));
            }
            #pragma unroll
            for (int mt = 0; mt < 4; mt++)
                #pragma unroll
                for (int nt = 0; nt < 8; nt++)
                    asm volatile(
                        "mma.sync.aligned.m16n8k8.row.col.f32.tf32.tf32.f32 "
                        "{%0,%1,%2,%3}, {%4,%5,%6,%7}, {%8,%9}, {%0,%1,%2,%3};"
                        : "+f"(acc[mt][nt][0]), "+f"(acc[mt][nt][1]),
                          "+f"(acc[mt][nt][2]), "+f"(acc[mt][nt][3])
                        : "r"(af[mt][0]), "r"(af[mt][1]), "r"(af[mt][2]), "r"(af[mt][3]),
                          "r"(bf[nt][0]), "r"(bf[nt][1]));
        }
    };

    // ---- pipelined mainloop --------------------------------------------------
    if (PRE == 3) fetchA(0);
    issue(0);
    if (PRE == 3) storeA(0);
    for (int c = 0; c < nch; c++) {
        if (c + 1 < nch) {
            issue(c + 1);
            if (PRE == 3) fetchA(c + 1);
            asm volatile("cp.async.wait_group 1;" ::: "memory");
        } else {
            asm volatile("cp.async.wait_group 0;" ::: "memory");
        }
        __syncthreads();
        compute(c & 1);
        __syncthreads();
        if (PRE == 3 && c + 1 < nch) storeA((c + 1) & 1);
    }

    // ---- epilogue ------------------------------------------------------------
    #pragma unroll
    for (int mt = 0; mt < 4; mt++) {
        int r0 = m0 + wm * 64 + mt * 16 + lr;
        int r1 = r0 + 8;
        float s0 = 1.f, s1 = 1.f;
        if (EROW) {
            if (r0 < M) s0 = escale[r0];
            if (r1 < M) s1 = escale[r1];
        }
        #pragma unroll
        for (int nt = 0; nt < 8; nt++) {
            int col = n0 + wn * 64 + nt * 8 + lc * 2;
            if (col >= Nn) continue;
            float bx = 0.f, by = 0.f;
            if (cbias) { bx = cbias[col]; by = cbias[col + 1]; }
            #pragma unroll
            for (int half = 0; half < 2; half++) {
                int row = half ? r1 : r0;
                if (row >= M) continue;
                float sc = half ? s1 : s0;
                float vx = acc[mt][nt][half * 2 + 0] * sc + bx;
                float vy = acc[mt][nt][half * 2 + 1] * sc + by;
                if (ACT == 1) { vx = fmaxf(vx, 0.f); vy = fmaxf(vy, 0.f); }
                else if (ACT == 2) {
                    vx = (vx > 0.f) ? vx : 0.2f * vx;
                    vy = (vy > 0.f) ? vy : 0.2f * vy;
                }
                if (ROUND) { vx = tf32r(vx); vy = tf32r(vy); }
                *(float2*)(C + (size_t)row * Nn + col) = make_float2(vx, vy);
            }
        }
    }
}

// ---------------- launch ------------------------------------------------------
static inline dim3 mm_grid(int M, int Nn) { return dim3((Nn + 127) / 128, (M + 127) / 128); }

extern "C" void kernel_launch(void* const* d_in, const int* in_sizes, int n_in,
                              void* d_out, int out_size)
{
    const float* x   = (const float*)d_in[0];
    const float* w   = (const float*)d_in[1];
    const int* src   = (const int*)d_in[2];
    const int* dst   = (const int*)d_in[3];
    const int* psrc  = (const int*)d_in[4];
    const int* pdst  = (const int*)d_in[5];
    const int* nsrc  = (const int*)d_in[6];
    const int* ndst  = (const int*)d_in[7];
    const float* W1  = (const float*)d_in[8];
    const float* b1  = (const float*)d_in[9];
    const float* W2  = (const float*)d_in[10];
    const float* b2  = (const float*)d_in[11];
    const float* W3  = (const float*)d_in[12];
    const float* b3  = (const float*)d_in[13];
    const float* P1  = (const float*)d_in[14];
    const float* pb1 = (const float*)d_in[15];
    const float* P2  = (const float*)d_in[16];
    const float* pb2 = (const float*)d_in[17];
    const float* P3  = (const float*)d_in[18];
    const float* pb3 = (const float*)d_in[19];

    float* out = (float*)d_out;
    float* out_h = out + NROWS_PAIR;   // [NPAIR pos | NPAIR neg | N*160 h]

    void *p_cntout, *p_cntin, *p_inorm;
    void *p_bufA, *p_bufB, *p_bufC, *p_M1, *p_M2, *p_Wt;
    cudaGetSymbolAddress(&p_cntout, g_cnt_out);
    cudaGetSymbolAddress(&p_cntin,  g_cnt_in);
    cudaGetSymbolAddress(&p_inorm,  g_inorm);
    cudaGetSymbolAddress(&p_bufA,   g_bufA);
    cudaGetSymbolAddress(&p_bufB,   g_bufB);
    cudaGetSymbolAddress(&p_bufC,   g_bufC);
    cudaGetSymbolAddress(&p_M1,     g_M1);
    cudaGetSymbolAddress(&p_M2,     g_M2);
    cudaGetSymbolAddress(&p_Wt,     g_Wt);
    float* inorm = (float*)p_inorm;
    float* bufA = (float*)p_bufA;
    float* bufB = (float*)p_bufB;
    float* bufC = (float*)p_bufC;
    float* M1b  = (float*)p_M1;
    float* M2b  = (float*)p_M2;
    float* W1t = (float*)p_Wt;
    float* W2t = W1t + 512 * 256;
    float* W3t = W2t + 256 * 512;
    float* P1t = W3t + 160 * 256;
    float* P2t = P1t + 80 * 160;

    cudaFuncSetAttribute(mm_gemm<0,1,1,1>, cudaFuncAttributeMaxDynamicSharedMemorySize, MM_SMEM_BYTES);
    cudaFuncSetAttribute(mm_gemm<0,0,0,0>, cudaFuncAttributeMaxDynamicSharedMemorySize, MM_SMEM_BYTES);
    cudaFuncSetAttribute(mm_gemm<3,0,2,1>, cudaFuncAttributeMaxDynamicSharedMemorySize, MM_SMEM_BYTES);
    cudaFuncSetAttribute(mm_gemm<0,0,2,0>, cudaFuncAttributeMaxDynamicSharedMemorySize, MM_SMEM_BYTES);

    const int E = NEDGES;

    // ---- graph preprocessing: counts -> norms -> CSR
    cudaMemsetAsync(p_cntout, 0, NNODES * sizeof(int));
    cudaMemsetAsync(p_cntin,  0, NNODES * sizeof(int));
    count_kernel<<<(E + 255) / 256, 256>>>(src, dst, E);
    norm_kernel<<<(NNODES + 255) / 256, 256>>>(NNODES);
    scan_kernel<<<1, 1024>>>();
    fill_kernel<<<(E + 255) / 256, 256>>>(src, dst, w, E);

    // weight transposes (tf32-rounded)
    transpose_kernel<<<(256*512 + 255) / 256, 256>>>(W1, W1t, 256, 512);
    transpose_kernel<<<(512*256 + 255) / 256, 256>>>(W2, W2t, 512, 256);
    transpose_kernel<<<(256*160 + 255) / 256, 256>>>(W3, W3t, 256, 160);
    transpose_kernel<<<(160*80  + 255) / 256, 256>>>(P1, P1t, 160, 80);
    transpose_kernel<<<(80*40   + 255) / 256, 256>>>(P2, P2t, 80, 40);

    const int agg_blocks = (NNODES * 32 + 255) / 256;

    // ---- layer 1: agg(x) [round] -> GEMM1: @W1, *inorm+b1, relu, round
    csr_agg_kernel<DIN, 0><<<agg_blocks, 256>>>(x, bufA, nullptr);
    mm_gemm<0,1,1,1><<<mm_grid(NNODES, H1DIM), 128, MM_SMEM_BYTES>>>(
        bufA, W1t, bufB, NNODES, DIN, H1DIM,
        inorm, b1, nullptr, nullptr, nullptr, nullptr);

    // ---- layer 2: GEMM2: h1@W2 -> agg2 with fused relu(*inorm+b2)+round
    mm_gemm<0,0,0,0><<<mm_grid(NNODES, H2DIM), 128, MM_SMEM_BYTES>>>(
        bufB, W2t, bufA, NNODES, H1DIM, H2DIM,
        nullptr, nullptr, nullptr, nullptr, nullptr, nullptr);
    csr_agg_kernel<H2DIM, 1><<<agg_blocks, 256>>>(bufA, bufC, b2);

    // ---- layer 3: GEMM3: bufC@W3 -> agg3 with fused *inorm+b3 -> out_h
    mm_gemm<0,0,0,0><<<mm_grid(NNODES, H3DIM), 128, MM_SMEM_BYTES>>>(
        bufC, W3t, bufB, NNODES, H2DIM, H3DIM,
        nullptr, nullptr, nullptr, nullptr, nullptr, nullptr);
    csr_agg_kernel<H3DIM, 2><<<agg_blocks, 256>>>(bufB, out_h, b3);

    // ---- predictor: fused pair-gather GEMM (160->80 leaky, round), 80->40 leaky, 40->1
    mm_gemm<3,0,2,1><<<mm_grid(NROWS_PAIR, 80), 128, MM_SMEM_BYTES>>>(
        out_h, P1t, M1b, NROWS_PAIR, H3DIM, 80,
        nullptr, pb1, psrc, pdst, nsrc, ndst);
    mm_gemm<0,0,2,0><<<mm_grid(NROWS_PAIR, 40), 128, MM_SMEM_BYTES>>>(
        M1b, P2t, M2b, NROWS_PAIR, 80, 40,
        nullptr, pb2, nullptr, nullptr, nullptr, nullptr);
    gemv_kernel<<<(NROWS_PAIR + 255) / 256, 256>>>(P3, pb3, out);
}

// round 11
// speedup vs baseline: 2.9351x; 1.3229x over previous
#include <cuda_runtime.h>
#include <stdint.h>

#define NNODES 50000
#define NEDGES 800000
#define NPAIRS 200000
#define DIN    256
#define H1DIM  512
#define H2DIM  256
#define H3DIM  160
#define NROWS_PAIR (2*NPAIRS)

// ---------------- scratch (static device globals; no allocation) -------------
__device__ int   g_cnt_out[NNODES];
__device__ int   g_cnt_in[NNODES];
__device__ float g_onorm[NNODES];
__device__ float g_inorm[NNODES];
__device__ int   g_rowptr[NNODES + 1];
__device__ int   g_cursor[NNODES];
__device__ int   g_csr_src[NEDGES];
__device__ float g_csr_w[NEDGES];
__device__ float g_bufA[(size_t)NNODES * 512];
__device__ float g_bufB[(size_t)NNODES * 512];
__device__ float g_bufC[(size_t)NNODES * 256];
__device__ float g_Wt[512*256 + 256*512 + 160*256 + 80*160 + 40*80];

// ---------------- helpers -----------------------------------------------------
static __device__ __forceinline__ float tf32r(float x) {
    uint32_t t;
    asm("cvt.rna.tf32.f32 %0, %1;" : "=r"(t) : "f"(x));
    return __uint_as_float(t);
}
static __device__ __forceinline__ uint32_t smem_u32(const void* p) {
    uint32_t a;
    asm("{ .reg .u64 t; cvta.to.shared.u64 t, %1; cvt.u32.u64 %0, t; }" : "=r"(a) : "l"(p));
    return a;
}

// ---------------- graph preprocessing ----------------------------------------
__global__ void count_kernel(const int* __restrict__ src, const int* __restrict__ dst, int E)
{
    int i = blockIdx.x * blockDim.x + threadIdx.x;
    if (i < E) {
        atomicAdd(&g_cnt_out[src[i]], 1);
        atomicAdd(&g_cnt_in [dst[i]], 1);
    }
}

__global__ void norm_kernel(int n)
{
    int i = blockIdx.x * blockDim.x + threadIdx.x;
    if (i < n) {
        g_onorm[i] = rsqrtf(fmaxf((float)g_cnt_out[i], 1.0f));
        g_inorm[i] = rsqrtf(fmaxf((float)g_cnt_in [i], 1.0f));
    }
}

__global__ void scan_kernel()
{
    __shared__ int sbuf[2][1024];
    __shared__ int carry;
    const int tid = threadIdx.x;
    if (tid == 0) carry = 0;
    __syncthreads();
    for (int base = 0; base < NNODES; base += 1024) {
        int v = (base + tid < NNODES) ? g_cnt_in[base + tid] : 0;
        int pi = 0;
        sbuf[0][tid] = v;
        __syncthreads();
        #pragma unroll
        for (int off = 1; off < 1024; off <<= 1) {
            int s = sbuf[pi][tid];
            if (tid >= off) s += sbuf[pi][tid - off];
            sbuf[pi ^ 1][tid] = s;
            pi ^= 1;
            __syncthreads();
        }
        int incl = sbuf[pi][tid];
        int excl = incl - v + carry;
        if (base + tid < NNODES) {
            g_rowptr[base + tid] = excl;
            g_cursor[base + tid] = excl;
        }
        __syncthreads();
        if (tid == 1023) carry += incl;
        __syncthreads();
    }
    if (tid == 0) g_rowptr[NNODES] = carry;
}

__global__ void fill_kernel(const int* __restrict__ src, const int* __restrict__ dst,
                            const float* __restrict__ w, int E)
{
    int i = blockIdx.x * blockDim.x + threadIdx.x;
    if (i < E) {
        int s = src[i];
        int slot = atomicAdd(&g_cursor[dst[i]], 1);
        g_csr_src[slot] = s;
        g_csr_w[slot]   = w[i] * g_onorm[s];
    }
}

// ---------------- CSR aggregation with fused epilogues ------------------------
// EPI: 0 = tf32-round(acc); 1 = tf32-round(relu(acc*inorm+bias)); 2 = acc*inorm+bias
template<int D, int EPI>
__global__ void csr_agg_kernel(const float* __restrict__ feat, float* __restrict__ outp,
                               const float* __restrict__ bias)
{
    const int node = (blockIdx.x * blockDim.x + threadIdx.x) >> 5;
    const int lane = threadIdx.x & 31;
    if (node >= NNODES) return;
    const int beg = g_rowptr[node], end = g_rowptr[node + 1];

    constexpr int NV = D / 4;
    constexpr bool HAS2 = (NV > 32);
    float4 acc0 = make_float4(0.f, 0.f, 0.f, 0.f);
    float4 acc1 = make_float4(0.f, 0.f, 0.f, 0.f);
    const bool use2 = HAS2 && (lane + 32 < NV);

    for (int base = beg; base < end; base += 32) {
        int cnt = min(32, end - base);
        int   sl = (lane < cnt) ? g_csr_src[base + lane] : 0;
        float wl = (lane < cnt) ? g_csr_w [base + lane] : 0.f;
        int j = 0;
        for (; j + 4 <= cnt; j += 4) {
            int   s0 = __shfl_sync(0xFFFFFFFFu, sl, j + 0);
            int   s1 = __shfl_sync(0xFFFFFFFFu, sl, j + 1);
            int   s2 = __shfl_sync(0xFFFFFFFFu, sl, j + 2);
            int   s3 = __shfl_sync(0xFFFFFFFFu, sl, j + 3);
            float w0 = __shfl_sync(0xFFFFFFFFu, wl, j + 0);
            float w1 = __shfl_sync(0xFFFFFFFFu, wl, j + 1);
            float w2 = __shfl_sync(0xFFFFFFFFu, wl, j + 2);
            float w3 = __shfl_sync(0xFFFFFFFFu, wl, j + 3);
            const float4* r0 = (const float4*)(feat + (size_t)s0 * D);
            const float4* r1 = (const float4*)(feat + (size_t)s1 * D);
            const float4* r2 = (const float4*)(feat + (size_t)s2 * D);
            const float4* r3 = (const float4*)(feat + (size_t)s3 * D);
            if (lane < NV) {
                float4 a0 = r0[lane], a1 = r1[lane], a2 = r2[lane], a3 = r3[lane];
                acc0.x += w0*a0.x + w1*a1.x + w2*a2.x + w3*a3.x;
                acc0.y += w0*a0.y + w1*a1.y + w2*a2.y + w3*a3.y;
                acc0.z += w0*a0.z + w1*a1.z + w2*a2.z + w3*a3.z;
                acc0.w += w0*a0.w + w1*a1.w + w2*a2.w + w3*a3.w;
            }
            if (use2) {
                float4 b0 = r0[lane+32], b1 = r1[lane+32], b2 = r2[lane+32], b3 = r3[lane+32];
                acc1.x += w0*b0.x + w1*b1.x + w2*b2.x + w3*b3.x;
                acc1.y += w0*b0.y + w1*b1.y + w2*b2.y + w3*b3.y;
                acc1.z += w0*b0.z + w1*b1.z + w2*b2.z + w3*b3.z;
                acc1.w += w0*b0.w + w1*b1.w + w2*b2.w + w3*b3.w;
            }
        }
        for (; j < cnt; j++) {
            int   s  = __shfl_sync(0xFFFFFFFFu, sl, j);
            float wv = __shfl_sync(0xFFFFFFFFu, wl, j);
            const float4* row = (const float4*)(feat + (size_t)s * D);
            if (lane < NV) {
                float4 a = row[lane];
                acc0.x += wv*a.x; acc0.y += wv*a.y; acc0.z += wv*a.z; acc0.w += wv*a.w;
            }
            if (use2) {
                float4 b = row[lane+32];
                acc1.x += wv*b.x; acc1.y += wv*b.y; acc1.z += wv*b.z; acc1.w += wv*b.w;
            }
        }
    }

    float nin = (EPI >= 1) ? g_inorm[node] : 1.0f;
    float4* orow = (float4*)(outp + (size_t)node * D);
    if (lane < NV) {
        float4 v = acc0;
        if (EPI >= 1) {
            float4 bb = *(const float4*)(bias + lane * 4);
            v.x = v.x * nin + bb.x; v.y = v.y * nin + bb.y;
            v.z = v.z * nin + bb.z; v.w = v.w * nin + bb.w;
            if (EPI == 1) {
                v.x = fmaxf(v.x, 0.f); v.y = fmaxf(v.y, 0.f);
                v.z = fmaxf(v.z, 0.f); v.w = fmaxf(v.w, 0.f);
            }
        }
        if (EPI != 2) { v.x = tf32r(v.x); v.y = tf32r(v.y); v.z = tf32r(v.z); v.w = tf32r(v.w); }
        orow[lane] = v;
    }
    if (use2) {
        float4 v = acc1;
        if (EPI >= 1) {
            float4 bb = *(const float4*)(bias + (lane + 32) * 4);
            v.x = v.x * nin + bb.x; v.y = v.y * nin + bb.y;
            v.z = v.z * nin + bb.z; v.w = v.w * nin + bb.w;
            if (EPI == 1) {
                v.x = fmaxf(v.x, 0.f); v.y = fmaxf(v.y, 0.f);
                v.z = fmaxf(v.z, 0.f); v.w = fmaxf(v.w, 0.f);
            }
        }
        if (EPI != 2) { v.x = tf32r(v.x); v.y = tf32r(v.y); v.z = tf32r(v.z); v.w = tf32r(v.w); }
        orow[lane + 32] = v;
    }
}

// ---------------- small kernels ----------------------------------------------
__global__ void transpose_kernel(const float* __restrict__ W, float* __restrict__ Wt, int K, int N)
{
    int i = blockIdx.x * blockDim.x + threadIdx.x;
    if (i < K * N) {
        int k = i / N, n = i - k * N;
        Wt[n * K + k] = tf32r(W[i]);
    }
}

// ---------------- tf32 mma.sync GEMM (4 warps, 64x64 warp tiles) -------------
#define SROW 36
#define SBUF (128 * SROW)
#define MM_SMEM_BYTES (4 * SBUF * 4)

template<int PRE, int EROW, int ACT, int ROUND>
__global__ __launch_bounds__(128)
void mm_gemm(const float* __restrict__ A, const float* __restrict__ Bt,
             float* __restrict__ C, int M, int K, int Nn,
             const float* __restrict__ escale, const float* __restrict__ cbias)
{
    extern __shared__ float smem[];
    float* sA = smem;
    float* sB = smem + 2 * SBUF;
    const uint32_t sAu = smem_u32(sA);
    const uint32_t sBu = smem_u32(sB);

    const int tid  = threadIdx.x;
    const int m0   = blockIdx.y * 128;
    const int n0   = blockIdx.x * 128;
    const int lane = tid & 31;
    const int wq   = tid >> 5;
    const int wm   = wq & 1;
    const int wn   = wq >> 1;
    const int lr   = lane >> 2;
    const int lc   = lane & 3;
    const int sub  = lane >> 3;
    const int rr   = lane & 7;
    const int nch  = (K + 31) / 32;

    float acc[4][8][4];
    #pragma unroll
    for (int mt = 0; mt < 4; mt++)
        #pragma unroll
        for (int nt = 0; nt < 8; nt++)
            #pragma unroll
            for (int r = 0; r < 4; r++) acc[mt][nt][r] = 0.0f;

    auto issue = [&](int c) {
        const int b = c & 1, k0 = c * 32;
        #pragma unroll
        for (int i = 0; i < 8; i++) {
            int idx = i * 128 + tid;
            int r = idx >> 3, kk = (idx & 7) * 4, gk = k0 + kk;
            uint32_t so = (uint32_t)(r * SROW + kk) * 4 + (uint32_t)b * (SBUF * 4);
            int gkc = min(gk, K - 4);
            int gm = m0 + r;
            int sz = ((gm < M) && (gk < K)) ? 16 : 0;
            const float* ga = A + (size_t)min(gm, M - 1) * K + gkc;
            asm volatile("cp.async.ca.shared.global [%0], [%1], 16, %2;"
                         :: "r"(sAu + so), "l"(ga), "r"(sz));
            int gn = n0 + r;
            int szb = ((gn < Nn) && (gk < K)) ? 16 : 0;
            const float* gb = Bt + (size_t)min(gn, Nn - 1) * K + gkc;
            asm volatile("cp.async.ca.shared.global [%0], [%1], 16, %2;"
                         :: "r"(sBu + so), "l"(gb), "r"(szb));
        }
        asm volatile("cp.async.commit_group;" ::: "memory");
    };

    auto compute = [&](int b) {
        const uint32_t baseA = sAu + (uint32_t)b * (SBUF * 4);
        const uint32_t baseB = sBu + (uint32_t)b * (SBUF * 4);
        #pragma unroll
        for (int ks = 0; ks < 4; ks++) {
            const int kb = ks * 8;
            uint32_t af[4][4], bf[8][2];
            #pragma unroll
            for (int mt = 0; mt < 4; mt++) {
                int row = wm * 64 + mt * 16 + rr + (sub & 1) * 8;
                int col = kb + (sub >> 1) * 4;
                uint32_t ad = baseA + (uint32_t)(row * SROW + col) * 4;
                asm volatile("ldmatrix.sync.aligned.m8n8.x4.shared.b16 {%0,%1,%2,%3}, [%4];"
                             : "=r"(af[mt][0]), "=r"(af[mt][1]), "=r"(af[mt][2]), "=r"(af[mt][3])
                             : "r"(ad));
            }
            #pragma unroll
            for (int ntp = 0; ntp < 4; ntp++) {
                int row = wn * 64 + ntp * 16 + rr + (sub >> 1) * 8;
                int col = kb + (sub & 1) * 4;
                uint32_t bd = baseB + (uint32_t)(row * SROW + col) * 4;
                asm volatile("ldmatrix.sync.aligned.m8n8.x4.shared.b16 {%0,%1,%2,%3}, [%4];"
                             : "=r"(bf[2*ntp][0]), "=r"(bf[2*ntp][1]),
                               "=r"(bf[2*ntp+1][0]), "=r"(bf[2*ntp+1][1])
                             : "r"(bd));
            }
            #pragma unroll
            for (int mt = 0; mt < 4; mt++)
                #pragma unroll
                for (int nt = 0; nt < 8; nt++)
                    asm volatile(
                        "mma.sync.aligned.m16n8k8.row.col.f32.tf32.tf32.f32 "
                        "{%0,%1,%2,%3}, {%4,%5,%6,%7}, {%8,%9}, {%0,%1,%2,%3};"
                        : "+f"(acc[mt][nt][0]), "+f"(acc[mt][nt][1]),
                          "+f"(acc[mt][nt][2]), "+f"(acc[mt][nt][3])
                        : "r"(af[mt][0]), "r"(af[mt][1]), "r"(af[mt][2]), "r"(af[mt][3]),
                          "r"(bf[nt][0]), "r"(bf[nt][1]));
        }
    };

    issue(0);
    for (int c = 0; c < nch; c++) {
        if (c + 1 < nch) {
            issue(c + 1);
            asm volatile("cp.async.wait_group 1;" ::: "memory");
        } else {
            asm volatile("cp.async.wait_group 0;" ::: "memory");
        }
        __syncthreads();
        compute(c & 1);
        __syncthreads();
    }

    #pragma unroll
    for (int mt = 0; mt < 4; mt++) {
        int r0 = m0 + wm * 64 + mt * 16 + lr;
        int r1 = r0 + 8;
        float s0 = 1.f, s1 = 1.f;
        if (EROW) {
            if (r0 < M) s0 = escale[r0];
            if (r1 < M) s1 = escale[r1];
        }
        #pragma unroll
        for (int nt = 0; nt < 8; nt++) {
            int col = n0 + wn * 64 + nt * 8 + lc * 2;
            if (col >= Nn) continue;
            float bx = 0.f, by = 0.f;
            if (cbias) { bx = cbias[col]; by = cbias[col + 1]; }
            #pragma unroll
            for (int half = 0; half < 2; half++) {
                int row = half ? r1 : r0;
                if (row >= M) continue;
                float sc = half ? s1 : s0;
                float vx = acc[mt][nt][half * 2 + 0] * sc + bx;
                float vy = acc[mt][nt][half * 2 + 1] * sc + by;
                if (ACT == 1) { vx = fmaxf(vx, 0.f); vy = fmaxf(vy, 0.f); }
                else if (ACT == 2) {
                    vx = (vx > 0.f) ? vx : 0.2f * vx;
                    vy = (vy > 0.f) ? vy : 0.2f * vy;
                }
                if (ROUND) { vx = tf32r(vx); vy = tf32r(vy); }
                *(float2*)(C + (size_t)row * Nn + col) = make_float2(vx, vy);
            }
        }
    }
}

// ---------------- fused predictor: pair-gather -> 160->80 -> 80->40 -> 40->1 --
// grid = 3125 CTAs x 128 threads; 3125*128 == NROWS_PAIR exactly (no bounds).
// smem: sAd[2][128][36] double-buffered A chunks (stage1), s1o[3][128][36]
// stage-1 output (chunked for ldmatrix), s2o[128][44] aliases sAd.
#define PF_CH (128 * 36)
#define PF_SMEM_BYTES (5 * PF_CH * 4)   // 92160

__global__ __launch_bounds__(128)
void pred_fused(const float* __restrict__ h3,
                const float* __restrict__ P1t, const float* __restrict__ pb1,
                const float* __restrict__ P2t, const float* __restrict__ pb2,
                const float* __restrict__ P3,  const float* __restrict__ pb3,
                const int* __restrict__ ips, const int* __restrict__ ipd,
                const int* __restrict__ ins, const int* __restrict__ ind,
                float* __restrict__ out)
{
    extern __shared__ float smem[];
    float* sAd = smem;                 // [2][PF_CH]
    float* s1o = smem + 2 * PF_CH;     // [3][PF_CH]
    float* s2o = smem;                 // alias over sAd (free after stage 1)
    const uint32_t sAu = smem_u32(sAd);
    const uint32_t s1u = smem_u32(s1o);

    const int tid  = threadIdx.x;
    const int r0   = blockIdx.x * 128;
    const int lane = tid & 31;
    const int wq   = tid >> 5;
    const int wm   = wq & 1;           // stage1: 64-row slab
    const int wn   = wq >> 1;          // stage1: 40-col slab
    const int lr   = lane >> 2;
    const int lc   = lane & 3;
    const int sub  = lane >> 3;
    const int rr   = lane & 7;

    // ---- stage 1: Z = (h3[ia]*h3[ib]) @ P1^T, leaky, round ------------------
    float4 rgA[8];
    auto fetchA = [&](int c) {
        const int k0 = c * 32;
        #pragma unroll
        for (int i = 0; i < 8; i++) {
            int idx = i * 128 + tid;
            int r = idx >> 3, kk = (idx & 7) * 4;
            int gm = r0 + r;
            int ia, ib;
            if (gm < NPAIRS) { ia = ips[gm]; ib = ipd[gm]; }
            else             { ia = ins[gm - NPAIRS]; ib = ind[gm - NPAIRS]; }
            float4 va = *(const float4*)(h3 + (size_t)ia * H3DIM + k0 + kk);
            float4 vb = *(const float4*)(h3 + (size_t)ib * H3DIM + k0 + kk);
            rgA[i] = make_float4(va.x*vb.x, va.y*vb.y, va.z*vb.z, va.w*vb.w);
        }
    };
    auto storeA = [&](int b) {
        #pragma unroll
        for (int i = 0; i < 8; i++) {
            int idx = i * 128 + tid;
            int r = idx >> 3, kk = (idx & 7) * 4;
            float4 v = rgA[i];
            v.x = tf32r(v.x); v.y = tf32r(v.y); v.z = tf32r(v.z); v.w = tf32r(v.w);
            *(float4*)(sAd + b * PF_CH + r * 36 + kk) = v;
        }
    };

    float a1[4][5][4];
    #pragma unroll
    for (int mt = 0; mt < 4; mt++)
        #pragma unroll
        for (int nt = 0; nt < 5; nt++)
            #pragma unroll
            for (int r = 0; r < 4; r++) a1[mt][nt][r] = 0.0f;

    auto compute1 = [&](int b, int c) {
        const uint32_t baseA = sAu + (uint32_t)b * (PF_CH * 4);
        #pragma unroll
        for (int ks = 0; ks < 4; ks++) {
            const int kb = ks * 8;
            const int kg = c * 32 + kb;
            uint32_t af[4][4], bf[5][2];
            #pragma unroll
            for (int mt = 0; mt < 4; mt++) {
                int row = wm * 64 + mt * 16 + rr + (sub & 1) * 8;
                int col = kb + (sub >> 1) * 4;
                uint32_t ad = baseA + (uint32_t)(row * 36 + col) * 4;
                asm volatile("ldmatrix.sync.aligned.m8n8.x4.shared.b16 {%0,%1,%2,%3}, [%4];"
                             : "=r"(af[mt][0]), "=r"(af[mt][1]), "=r"(af[mt][2]), "=r"(af[mt][3])
                             : "r"(ad));
            }
            #pragma unroll
            for (int nt = 0; nt < 5; nt++) {
                int n = wn * 40 + nt * 8 + lr;
                const float* bp = P1t + n * 160 + kg + lc;
                bf[nt][0] = __float_as_uint(__ldg(bp));
                bf[nt][1] = __float_as_uint(__ldg(bp + 4));
            }
            #pragma unroll
            for (int mt = 0; mt < 4; mt++)
                #pragma unroll
                for (int nt = 0; nt < 5; nt++)
                    asm volatile(
                        "mma.sync.aligned.m16n8k8.row.col.f32.tf32.tf32.f32 "
                        "{%0,%1,%2,%3}, {%4,%5,%6,%7}, {%8,%9}, {%0,%1,%2,%3};"
                        : "+f"(a1[mt][nt][0]), "+f"(a1[mt][nt][1]),
                          "+f"(a1[mt][nt][2]), "+f"(a1[mt][nt][3])
                        : "r"(af[mt][0]), "r"(af[mt][1]), "r"(af[mt][2]), "r"(af[mt][3]),
                          "r"(bf[nt][0]), "r"(bf[nt][1]));
        }
    };

    fetchA(0);
    storeA(0);
    for (int c = 0; c < 5; c++) {
        __syncthreads();
        if (c + 1 < 5) fetchA(c + 1);
        compute1(c & 1, c);
        if (c + 1 < 5) {
            __syncthreads();
            storeA((c + 1) & 1);
        }
    }

    // epilogue 1 -> s1o (chunked layout, cols 0..79)
    #pragma unroll
    for (int mt = 0; mt < 4; mt++) {
        int row0 = wm * 64 + mt * 16 + lr;
        #pragma unroll
        for (int nt = 0; nt < 5; nt++) {
            int col = wn * 40 + nt * 8 + lc * 2;
            float bx = pb1[col], by = pb1[col + 1];
            int ch = col >> 5, ci = col & 31;
            #pragma unroll
            for (int half = 0; half < 2; half++) {
                int row = row0 + half * 8;
                float vx = a1[mt][nt][half * 2 + 0] + bx;
                float vy = a1[mt][nt][half * 2 + 1] + by;
                vx = (vx > 0.f) ? vx : 0.2f * vx;
                vy = (vy > 0.f) ? vy : 0.2f * vy;
                vx = tf32r(vx); vy = tf32r(vy);
                *(float2*)(s1o + ch * PF_CH + row * 36 + ci) = make_float2(vx, vy);
            }
        }
    }
    __syncthreads();

    // ---- stage 2: H = leaky(Z1 @ P2^T + pb2); warp = 32 rows x 40 cols ------
    float a2[2][5][4];
    #pragma unroll
    for (int mt = 0; mt < 2; mt++)
        #pragma unroll
        for (int nt = 0; nt < 5; nt++)
            #pragma unroll
            for (int r = 0; r < 4; r++) a2[mt][nt][r] = 0.0f;

    #pragma unroll
    for (int ch = 0; ch < 3; ch++) {
        const int nks = (ch < 2) ? 4 : 2;
        const uint32_t baseA = s1u + (uint32_t)ch * (PF_CH * 4);
        for (int ks = 0; ks < nks; ks++) {
            const int kb = ks * 8;
            const int kg = ch * 32 + kb;
            uint32_t af[2][4], bf[5][2];
            #pragma unroll
            for (int mt = 0; mt < 2; mt++) {
                int row = wq * 32 + mt * 16 + rr + (sub & 1) * 8;
                int col = kb + (sub >> 1) * 4;
                uint32_t ad = baseA + (uint32_t)(row * 36 + col) * 4;
                asm volatile("ldmatrix.sync.aligned.m8n8.x4.shared.b16 {%0,%1,%2,%3}, [%4];"
                             : "=r"(af[mt][0]), "=r"(af[mt][1]), "=r"(af[mt][2]), "=r"(af[mt][3])
                             : "r"(ad));
            }
            #pragma unroll
            for (int nt = 0; nt < 5; nt++) {
                int n = nt * 8 + lr;
                const float* bp = P2t + n * 80 + kg + lc;
                bf[nt][0] = __float_as_uint(__ldg(bp));
                bf[nt][1] = __float_as_uint(__ldg(bp + 4));
            }
            #pragma unroll
            for (int mt = 0; mt < 2; mt++)
                #pragma unroll
                for (int nt = 0; nt < 5; nt++)
                    asm volatile(
                        "mma.sync.aligned.m16n8k8.row.col.f32.tf32.tf32.f32 "
                        "{%0,%1,%2,%3}, {%4,%5,%6,%7}, {%8,%9}, {%0,%1,%2,%3};"
                        : "+f"(a2[mt][nt][0]), "+f"(a2[mt][nt][1]),
                          "+f"(a2[mt][nt][2]), "+f"(a2[mt][nt][3])
                        : "r"(af[mt][0]), "r"(af[mt][1]), "r"(af[mt][2]), "r"(af[mt][3]),
                          "r"(bf[nt][0]), "r"(bf[nt][1]));
        }
    }

    // epilogue 2 -> s2o (row-major stride 44)
    #pragma unroll
    for (int mt = 0; mt < 2; mt++) {
        int row0 = wq * 32 + mt * 16 + lr;
        #pragma unroll
        for (int nt = 0; nt < 5; nt++) {
            int col = nt * 8 + lc * 2;
            float bx = pb2[col], by = pb2[col + 1];
            #pragma unroll
            for (int half = 0; half < 2; half++) {
                int row = row0 + half * 8;
                float vx = a2[mt][nt][half * 2 + 0] + bx;
                float vy = a2[mt][nt][half * 2 + 1] + by;
                vx = (vx > 0.f) ? vx : 0.2f * vx;
                vy = (vy > 0.f) ? vy : 0.2f * vy;
                *(float2*)(s2o + row * 44 + col) = make_float2(vx, vy);
            }
        }
    }
    __syncthreads();

    // ---- stage 3: out = H @ P3 + pb3 (one thread per row) -------------------
    float acc = __ldg(pb3);
    const float* rowp = s2o + tid * 44;
    #pragma unroll
    for (int k = 0; k < 40; k += 4) {
        float4 v = *(const float4*)(rowp + k);
        acc += v.x * __ldg(P3 + k + 0) + v.y * __ldg(P3 + k + 1)
             + v.z * __ldg(P3 + k + 2) + v.w * __ldg(P3 + k + 3);
    }
    out[r0 + tid] = acc;
}

// ---------------- launch ------------------------------------------------------
static inline dim3 mm_grid(int M, int Nn) { return dim3((Nn + 127) / 128, (M + 127) / 128); }

extern "C" void kernel_launch(void* const* d_in, const int* in_sizes, int n_in,
                              void* d_out, int out_size)
{
    const float* x   = (const float*)d_in[0];
    const float* w   = (const float*)d_in[1];
    const int* src   = (const int*)d_in[2];
    const int* dst   = (const int*)d_in[3];
    const int* psrc  = (const int*)d_in[4];
    const int* pdst  = (const int*)d_in[5];
    const int* nsrc  = (const int*)d_in[6];
    const int* ndst  = (const int*)d_in[7];
    const float* W1  = (const float*)d_in[8];
    const float* b1  = (const float*)d_in[9];
    const float* W2  = (const float*)d_in[10];
    const float* b2  = (const float*)d_in[11];
    const float* W3  = (const float*)d_in[12];
    const float* b3  = (const float*)d_in[13];
    const float* P1  = (const float*)d_in[14];
    const float* pb1 = (const float*)d_in[15];
    const float* P2  = (const float*)d_in[16];
    const float* pb2 = (const float*)d_in[17];
    const float* P3  = (const float*)d_in[18];
    const float* pb3 = (const float*)d_in[19];

    float* out = (float*)d_out;
    float* out_h = out + NROWS_PAIR;   // [NPAIR pos | NPAIR neg | N*160 h]

    void *p_cntout, *p_cntin, *p_inorm;
    void *p_bufA, *p_bufB, *p_bufC, *p_Wt;
    cudaGetSymbolAddress(&p_cntout, g_cnt_out);
    cudaGetSymbolAddress(&p_cntin,  g_cnt_in);
    cudaGetSymbolAddress(&p_inorm,  g_inorm);
    cudaGetSymbolAddress(&p_bufA,   g_bufA);
    cudaGetSymbolAddress(&p_bufB,   g_bufB);
    cudaGetSymbolAddress(&p_bufC,   g_bufC);
    cudaGetSymbolAddress(&p_Wt,     g_Wt);
    float* inorm = (float*)p_inorm;
    float* bufA = (float*)p_bufA;
    float* bufB = (float*)p_bufB;
    float* bufC = (float*)p_bufC;
    float* W1t = (float*)p_Wt;
    float* W2t = W1t + 512 * 256;
    float* W3t = W2t + 256 * 512;
    float* P1t = W3t + 160 * 256;
    float* P2t = P1t + 80 * 160;

    cudaFuncSetAttribute(mm_gemm<0,1,1,1>, cudaFuncAttributeMaxDynamicSharedMemorySize, MM_SMEM_BYTES);
    cudaFuncSetAttribute(mm_gemm<0,0,0,0>, cudaFuncAttributeMaxDynamicSharedMemorySize, MM_SMEM_BYTES);
    cudaFuncSetAttribute(pred_fused, cudaFuncAttributeMaxDynamicSharedMemorySize, PF_SMEM_BYTES);

    const int E = NEDGES;

    // ---- graph preprocessing: counts -> norms -> CSR
    cudaMemsetAsync(p_cntout, 0, NNODES * sizeof(int));
    cudaMemsetAsync(p_cntin,  0, NNODES * sizeof(int));
    count_kernel<<<(E + 255) / 256, 256>>>(src, dst, E);
    norm_kernel<<<(NNODES + 255) / 256, 256>>>(NNODES);
    scan_kernel<<<1, 1024>>>();
    fill_kernel<<<(E + 255) / 256, 256>>>(src, dst, w, E);

    // weight transposes (tf32-rounded)
    transpose_kernel<<<(256*512 + 255) / 256, 256>>>(W1, W1t, 256, 512);
    transpose_kernel<<<(512*256 + 255) / 256, 256>>>(W2, W2t, 512, 256);
    transpose_kernel<<<(256*160 + 255) / 256, 256>>>(W3, W3t, 256, 160);
    transpose_kernel<<<(160*80  + 255) / 256, 256>>>(P1, P1t, 160, 80);
    transpose_kernel<<<(80*40   + 255) / 256, 256>>>(P2, P2t, 80, 40);

    const int agg_blocks = (NNODES * 32 + 255) / 256;

    // ---- layer 1: agg(x) [round] -> GEMM1: @W1, *inorm+b1, relu, round
    csr_agg_kernel<DIN, 0><<<agg_blocks, 256>>>(x, bufA, nullptr);
    mm_gemm<0,1,1,1><<<mm_grid(NNODES, H1DIM), 128, MM_SMEM_BYTES>>>(
        bufA, W1t, bufB, NNODES, DIN, H1DIM, inorm, b1);

    // ---- layer 2: GEMM2: h1@W2 -> agg2 with fused relu(*inorm+b2)+round
    mm_gemm<0,0,0,0><<<mm_grid(NNODES, H2DIM), 128, MM_SMEM_BYTES>>>(
        bufB, W2t, bufA, NNODES, H1DIM, H2DIM, nullptr, nullptr);
    csr_agg_kernel<H2DIM, 1><<<agg_blocks, 256>>>(bufA, bufC, b2);

    // ---- layer 3: GEMM3: bufC@W3 -> agg3 with fused *inorm+b3 -> out_h
    mm_gemm<0,0,0,0><<<mm_grid(NNODES, H3DIM), 128, MM_SMEM_BYTES>>>(
        bufC, W3t, bufB, NNODES, H2DIM, H3DIM, nullptr, nullptr);
    csr_agg_kernel<H3DIM, 2><<<agg_blocks, 256>>>(bufB, out_h, b3);

    // ---- fused predictor: one launch for P1/P2/P3
    pred_fused<<<NROWS_PAIR / 128, 128, PF_SMEM_BYTES>>>(
        out_h, P1t, pb1, P2t, pb2, P3, pb3, psrc, pdst, nsrc, ndst, out);
}

// round 12
// speedup vs baseline: 3.2217x; 1.0977x over previous
#include <cuda_runtime.h>
#include <stdint.h>

#define NNODES 50000
#define NEDGES 800000
#define NPAIRS 200000
#define DIN    256
#define H1DIM  512
#define H2DIM  256
#define H3DIM  160
#define NROWS_PAIR (2*NPAIRS)
#define SCAN_BLOCKS ((NNODES + 255) / 256)   // 196

// ---------------- scratch (static device globals; no allocation) -------------
__device__ int   g_cnt_out[NNODES];
__device__ int   g_cnt_in[NNODES];
__device__ float g_onorm[NNODES];
__device__ float g_inorm[NNODES];
__device__ int   g_bsum[SCAN_BLOCKS];
__device__ int   g_bsumx[SCAN_BLOCKS];
__device__ int   g_rowptr[NNODES + 1];
__device__ int   g_cursor[NNODES];
__device__ int   g_csr_src[NEDGES];
__device__ float g_csr_w[NEDGES];
__device__ float g_bufA[(size_t)NNODES * 512];
__device__ float g_bufB[(size_t)NNODES * 512];
__device__ float g_bufC[(size_t)NNODES * 256];
__device__ float g_Wt[512*256 + 256*512 + 160*256 + 80*160 + 40*80];

// ---------------- helpers -----------------------------------------------------
static __device__ __forceinline__ float tf32r(float x) {
    uint32_t t;
    asm("cvt.rna.tf32.f32 %0, %1;" : "=r"(t) : "f"(x));
    return __uint_as_float(t);
}
static __device__ __forceinline__ uint32_t smem_u32(const void* p) {
    uint32_t a;
    asm("{ .reg .u64 t; cvta.to.shared.u64 t, %1; cvt.u32.u64 %0, t; }" : "=r"(a) : "l"(p));
    return a;
}
static __device__ __forceinline__ int block_excl_scan(int v, int tid) {
    __shared__ int ws[8];
    int lane = tid & 31, wid = tid >> 5;
    int x = v;
    #pragma unroll
    for (int off = 1; off < 32; off <<= 1) {
        int y = __shfl_up_sync(0xFFFFFFFFu, x, off);
        if (lane >= off) x += y;
    }
    if (lane == 31) ws[wid] = x;
    __syncthreads();
    if (wid == 0) {
        int s = (lane < 8) ? ws[lane] : 0;
        #pragma unroll
        for (int off = 1; off < 8; off <<= 1) {
            int y = __shfl_up_sync(0xFFFFFFFFu, s, off);
            if (lane >= off) s += y;
        }
        if (lane < 8) ws[lane] = s;
    }
    __syncthreads();
    int base = (wid > 0) ? ws[wid - 1] : 0;
    return base + x - v;
}

// ---------------- graph preprocessing ----------------------------------------
__global__ void count_kernel(const int* __restrict__ src, const int* __restrict__ dst, int E)
{
    int i = blockIdx.x * blockDim.x + threadIdx.x;
    if (i < E) {
        atomicAdd(&g_cnt_out[src[i]], 1);
        atomicAdd(&g_cnt_in [dst[i]], 1);
    }
}

// phase 1: norms + per-block sums of cnt_in
__global__ void scan_phase1()
{
    __shared__ int ws[8];
    int tid = threadIdx.x;
    int i = blockIdx.x * 256 + tid;
    int v = 0;
    if (i < NNODES) {
        v = g_cnt_in[i];
        g_onorm[i] = rsqrtf(fmaxf((float)g_cnt_out[i], 1.0f));
        g_inorm[i] = rsqrtf(fmaxf((float)v, 1.0f));
    }
    int lane = tid & 31, wid = tid >> 5;
    int s = v;
    #pragma unroll
    for (int off = 16; off > 0; off >>= 1) s += __shfl_down_sync(0xFFFFFFFFu, s, off);
    if (lane == 0) ws[wid] = s;
    __syncthreads();
    if (tid == 0) {
        int t = 0;
        #pragma unroll
        for (int j = 0; j < 8; j++) t += ws[j];
        g_bsum[blockIdx.x] = t;
    }
}

// phase 2: exclusive scan of block sums (1 block, 256 threads >= 196)
__global__ void scan_phase2()
{
    int tid = threadIdx.x;
    int v = (tid < SCAN_BLOCKS) ? g_bsum[tid] : 0;
    int e = block_excl_scan(v, tid);
    if (tid < SCAN_BLOCKS) g_bsumx[tid] = e;
}

// phase 3: per-block exclusive scan + offset -> rowptr/cursor
__global__ void scan_phase3()
{
    int tid = threadIdx.x;
    int i = blockIdx.x * 256 + tid;
    int v = (i < NNODES) ? g_cnt_in[i] : 0;
    int e = block_excl_scan(v, tid) + g_bsumx[blockIdx.x];
    if (i < NNODES) { g_rowptr[i] = e; g_cursor[i] = e; }
    if (i == 0) g_rowptr[NNODES] = NEDGES;
}

__global__ void fill_kernel(const int* __restrict__ src, const int* __restrict__ dst,
                            const float* __restrict__ w, int E)
{
    int i = blockIdx.x * blockDim.x + threadIdx.x;
    if (i < E) {
        int s = src[i];
        int slot = atomicAdd(&g_cursor[dst[i]], 1);
        g_csr_src[slot] = s;
        g_csr_w[slot]   = w[i] * g_onorm[s];
    }
}

// ---------------- single merged weight transpose ------------------------------
// segments: (K,N): W1 256x512, W2 512x256, W3 256x160, P1 160x80, P2 80x40
#define TW1 (256*512)
#define TW2 (TW1 + 512*256)
#define TW3 (TW2 + 256*160)
#define TP1 (TW3 + 160*80)
#define TP2 (TP1 + 80*40)
__global__ void transpose_all(const float* __restrict__ W1, const float* __restrict__ W2,
                              const float* __restrict__ W3, const float* __restrict__ P1,
                              const float* __restrict__ P2, float* __restrict__ Wt)
{
    int i = blockIdx.x * blockDim.x + threadIdx.x;
    if (i >= TP2) return;
    const float* Wsrc; int K, N, base, off;
    if (i < TW1)      { Wsrc = W1; K = 256; N = 512; base = 0;   off = i; }
    else if (i < TW2) { Wsrc = W2; K = 512; N = 256; base = TW1; off = i - TW1; }
    else if (i < TW3) { Wsrc = W3; K = 256; N = 160; base = TW2; off = i - TW2; }
    else if (i < TP1) { Wsrc = P1; K = 160; N = 80;  base = TW3; off = i - TW3; }
    else              { Wsrc = P2; K = 80;  N = 40;  base = TP1; off = i - TP1; }
    int k = off / N, n = off - k * N;
    Wt[base + n * K + k] = tf32r(Wsrc[off]);
}

// ---------------- CSR aggregation with fused epilogues ------------------------
// EPI: 0 = tf32-round(acc); 1 = tf32-round(relu(acc*inorm+bias)); 2 = acc*inorm+bias
template<int D, int EPI>
__global__ void csr_agg_kernel(const float* __restrict__ feat, float* __restrict__ outp,
                               const float* __restrict__ bias)
{
    const int node = (blockIdx.x * blockDim.x + threadIdx.x) >> 5;
    const int lane = threadIdx.x & 31;
    if (node >= NNODES) return;
    const int beg = g_rowptr[node], end = g_rowptr[node + 1];

    constexpr int NV = D / 4;
    constexpr bool HAS2 = (NV > 32);
    float4 acc0 = make_float4(0.f, 0.f, 0.f, 0.f);
    float4 acc1 = make_float4(0.f, 0.f, 0.f, 0.f);
    const bool use2 = HAS2 && (lane + 32 < NV);

    for (int base = beg; base < end; base += 32) {
        int cnt = min(32, end - base);
        int   sl = (lane < cnt) ? g_csr_src[base + lane] : 0;
        float wl = (lane < cnt) ? g_csr_w [base + lane] : 0.f;
        int j = 0;
        for (; j + 4 <= cnt; j += 4) {
            int   s0 = __shfl_sync(0xFFFFFFFFu, sl, j + 0);
            int   s1 = __shfl_sync(0xFFFFFFFFu, sl, j + 1);
            int   s2 = __shfl_sync(0xFFFFFFFFu, sl, j + 2);
            int   s3 = __shfl_sync(0xFFFFFFFFu, sl, j + 3);
            float w0 = __shfl_sync(0xFFFFFFFFu, wl, j + 0);
            float w1 = __shfl_sync(0xFFFFFFFFu, wl, j + 1);
            float w2 = __shfl_sync(0xFFFFFFFFu, wl, j + 2);
            float w3 = __shfl_sync(0xFFFFFFFFu, wl, j + 3);
            const float4* r0 = (const float4*)(feat + (size_t)s0 * D);
            const float4* r1 = (const float4*)(feat + (size_t)s1 * D);
            const float4* r2 = (const float4*)(feat + (size_t)s2 * D);
            const float4* r3 = (const float4*)(feat + (size_t)s3 * D);
            if (lane < NV) {
                float4 a0 = r0[lane], a1 = r1[lane], a2 = r2[lane], a3 = r3[lane];
                acc0.x += w0*a0.x + w1*a1.x + w2*a2.x + w3*a3.x;
                acc0.y += w0*a0.y + w1*a1.y + w2*a2.y + w3*a3.y;
                acc0.z += w0*a0.z + w1*a1.z + w2*a2.z + w3*a3.z;
                acc0.w += w0*a0.w + w1*a1.w + w2*a2.w + w3*a3.w;
            }
            if (use2) {
                float4 b0 = r0[lane+32], b1 = r1[lane+32], b2 = r2[lane+32], b3 = r3[lane+32];
                acc1.x += w0*b0.x + w1*b1.x + w2*b2.x + w3*b3.x;
                acc1.y += w0*b0.y + w1*b1.y + w2*b2.y + w3*b3.y;
                acc1.z += w0*b0.z + w1*b1.z + w2*b2.z + w3*b3.z;
                acc1.w += w0*b0.w + w1*b1.w + w2*b2.w + w3*b3.w;
            }
        }
        for (; j < cnt; j++) {
            int   s  = __shfl_sync(0xFFFFFFFFu, sl, j);
            float wv = __shfl_sync(0xFFFFFFFFu, wl, j);
            const float4* row = (const float4*)(feat + (size_t)s * D);
            if (lane < NV) {
                float4 a = row[lane];
                acc0.x += wv*a.x; acc0.y += wv*a.y; acc0.z += wv*a.z; acc0.w += wv*a.w;
            }
            if (use2) {
                float4 b = row[lane+32];
                acc1.x += wv*b.x; acc1.y += wv*b.y; acc1.z += wv*b.z; acc1.w += wv*b.w;
            }
        }
    }

    float nin = (EPI >= 1) ? g_inorm[node] : 1.0f;
    float4* orow = (float4*)(outp + (size_t)node * D);
    if (lane < NV) {
        float4 v = acc0;
        if (EPI >= 1) {
            float4 bb = *(const float4*)(bias + lane * 4);
            v.x = v.x * nin + bb.x; v.y = v.y * nin + bb.y;
            v.z = v.z * nin + bb.z; v.w = v.w * nin + bb.w;
            if (EPI == 1) {
                v.x = fmaxf(v.x, 0.f); v.y = fmaxf(v.y, 0.f);
                v.z = fmaxf(v.z, 0.f); v.w = fmaxf(v.w, 0.f);
            }
        }
        if (EPI != 2) { v.x = tf32r(v.x); v.y = tf32r(v.y); v.z = tf32r(v.z); v.w = tf32r(v.w); }
        orow[lane] = v;
    }
    if (use2) {
        float4 v = acc1;
        if (EPI >= 1) {
            float4 bb = *(const float4*)(bias + (lane + 32) * 4);
            v.x = v.x * nin + bb.x; v.y = v.y * nin + bb.y;
            v.z = v.z * nin + bb.z; v.w = v.w * nin + bb.w;
            if (EPI == 1) {
                v.x = fmaxf(v.x, 0.f); v.y = fmaxf(v.y, 0.f);
                v.z = fmaxf(v.z, 0.f); v.w = fmaxf(v.w, 0.f);
            }
        }
        if (EPI != 2) { v.x = tf32r(v.x); v.y = tf32r(v.y); v.z = tf32r(v.z); v.w = tf32r(v.w); }
        orow[lane + 32] = v;
    }
}

// ---------------- tf32 mma.sync GEMM (4 warps; NT = CTA N-tile 128 or 64) -----
#define SROW 36
#define SBUF (128 * SROW)

template<int EROW, int ACT, int ROUND, int NT>
__global__ __launch_bounds__(128)
void mm_gemm(const float* __restrict__ A, const float* __restrict__ Bt,
             float* __restrict__ C, int M, int K, int Nn,
             const float* __restrict__ escale, const float* __restrict__ cbias)
{
    constexpr int BS  = NT * SROW;       // B buffer floats
    constexpr int WNW = NT / 2;          // warp n-width (64 or 32)
    constexpr int NTFR = WNW / 8;        // n fragments per warp (8 or 4)
    extern __shared__ float smem[];
    float* sA = smem;                    // [2][SBUF]
    float* sB = smem + 2 * SBUF;         // [2][BS]
    const uint32_t sAu = smem_u32(sA);
    const uint32_t sBu = smem_u32(sB);

    const int tid  = threadIdx.x;
    const int m0   = blockIdx.y * 128;
    const int n0   = blockIdx.x * NT;
    const int lane = tid & 31;
    const int wq   = tid >> 5;
    const int wm   = wq & 1;
    const int wn   = wq >> 1;
    const int lr   = lane >> 2;
    const int lc   = lane & 3;
    const int sub  = lane >> 3;
    const int rr   = lane & 7;
    const int nch  = (K + 31) / 32;

    float acc[4][NTFR][4];
    #pragma unroll
    for (int mt = 0; mt < 4; mt++)
        #pragma unroll
        for (int nt = 0; nt < NTFR; nt++)
            #pragma unroll
            for (int r = 0; r < 4; r++) acc[mt][nt][r] = 0.0f;

    auto issue = [&](int c) {
        const int b = c & 1, k0 = c * 32;
        #pragma unroll
        for (int i = 0; i < 8; i++) {
            int idx = i * 128 + tid;
            int r = idx >> 3, kk = (idx & 7) * 4, gk = k0 + kk;
            uint32_t so = (uint32_t)(r * SROW + kk) * 4 + (uint32_t)b * (SBUF * 4);
            int gkc = min(gk, K - 4);
            int gm = m0 + r;
            int sz = ((gm < M) && (gk < K)) ? 16 : 0;
            const float* ga = A + (size_t)min(gm, M - 1) * K + gkc;
            asm volatile("cp.async.ca.shared.global [%0], [%1], 16, %2;"
                         :: "r"(sAu + so), "l"(ga), "r"(sz));
        }
        #pragma unroll
        for (int i = 0; i < NT / 16; i++) {
            int idx = i * 128 + tid;
            int r = idx >> 3, kk = (idx & 7) * 4, gk = k0 + kk;
            uint32_t so = (uint32_t)(r * SROW + kk) * 4 + (uint32_t)b * (BS * 4);
            int gkc = min(gk, K - 4);
            int gn = n0 + r;
            int szb = ((gn < Nn) && (gk < K)) ? 16 : 0;
            const float* gb = Bt + (size_t)min(gn, Nn - 1) * K + gkc;
            asm volatile("cp.async.ca.shared.global [%0], [%1], 16, %2;"
                         :: "r"(sBu + so), "l"(gb), "r"(szb));
        }
        asm volatile("cp.async.commit_group;" ::: "memory");
    };

    auto compute = [&](int b) {
        const uint32_t baseA = sAu + (uint32_t)b * (SBUF * 4);
        const uint32_t baseB = sBu + (uint32_t)b * (BS * 4);
        #pragma unroll
        for (int ks = 0; ks < 4; ks++) {
            const int kb = ks * 8;
            uint32_t af[4][4], bf[NTFR][2];
            #pragma unroll
            for (int mt = 0; mt < 4; mt++) {
                int row = wm * 64 + mt * 16 + rr + (sub & 1) * 8;
                int col = kb + (sub >> 1) * 4;
                uint32_t ad = baseA + (uint32_t)(row * SROW + col) * 4;
                asm volatile("ldmatrix.sync.aligned.m8n8.x4.shared.b16 {%0,%1,%2,%3}, [%4];"
                             : "=r"(af[mt][0]), "=r"(af[mt][1]), "=r"(af[mt][2]), "=r"(af[mt][3])
                             : "r"(ad));
            }
            #pragma unroll
            for (int ntp = 0; ntp < NTFR / 2; ntp++) {
                int row = wn * WNW + ntp * 16 + rr + (sub >> 1) * 8;
                int col = kb + (sub & 1) * 4;
                uint32_t bd = baseB + (uint32_t)(row * SROW + col) * 4;
                asm volatile("ldmatrix.sync.aligned.m8n8.x4.shared.b16 {%0,%1,%2,%3}, [%4];"
                             : "=r"(bf[2*ntp][0]), "=r"(bf[2*ntp][1]),
                               "=r"(bf[2*ntp+1][0]), "=r"(bf[2*ntp+1][1])
                             : "r"(bd));
            }
            #pragma unroll
            for (int mt = 0; mt < 4; mt++)
                #pragma unroll
                for (int nt = 0; nt < NTFR; nt++)
                    asm volatile(
                        "mma.sync.aligned.m16n8k8.row.col.f32.tf32.tf32.f32 "
                        "{%0,%1,%2,%3}, {%4,%5,%6,%7}, {%8,%9}, {%0,%1,%2,%3};"
                        : "+f"(acc[mt][nt][0]), "+f"(acc[mt][nt][1]),
                          "+f"(acc[mt][nt][2]), "+f"(acc[mt][nt][3])
                        : "r"(af[mt][0]), "r"(af[mt][1]), "r"(af[mt][2]), "r"(af[mt][3]),
                          "r"(bf[nt][0]), "r"(bf[nt][1]));
        }
    };

    issue(0);
    for (int c = 0; c < nch; c++) {
        if (c + 1 < nch) {
            issue(c + 1);
            asm volatile("cp.async.wait_group 1;" ::: "memory");
        } else {
            asm volatile("cp.async.wait_group 0;" ::: "memory");
        }
        __syncthreads();
        compute(c & 1);
        __syncthreads();
    }

    #pragma unroll
    for (int mt = 0; mt < 4; mt++) {
        int r0 = m0 + wm * 64 + mt * 16 + lr;
        int r1 = r0 + 8;
        float s0 = 1.f, s1 = 1.f;
        if (EROW) {
            if (r0 < M) s0 = escale[r0];
            if (r1 < M) s1 = escale[r1];
        }
        #pragma unroll
        for (int nt = 0; nt < NTFR; nt++) {
            int col = n0 + wn * WNW + nt * 8 + lc * 2;
            if (col >= Nn) continue;
            float bx = 0.f, by = 0.f;
            if (cbias) { bx = cbias[col]; by = cbias[col + 1]; }
            #pragma unroll
            for (int half = 0; half < 2; half++) {
                int row = half ? r1 : r0;
                if (row >= M) continue;
                float sc = half ? s1 : s0;
                float vx = acc[mt][nt][half * 2 + 0] * sc + bx;
                float vy = acc[mt][nt][half * 2 + 1] * sc + by;
                if (ACT == 1) { vx = fmaxf(vx, 0.f); vy = fmaxf(vy, 0.f); }
                else if (ACT == 2) {
                    vx = (vx > 0.f) ? vx : 0.2f * vx;
                    vy = (vy > 0.f) ? vy : 0.2f * vy;
                }
                if (ROUND) { vx = tf32r(vx); vy = tf32r(vy); }
                *(float2*)(C + (size_t)row * Nn + col) = make_float2(vx, vy);
            }
        }
    }
}
#define MM_SMEM(NT) ((2 * SBUF + 2 * (NT) * SROW) * 4)

// ---------------- fused predictor: pair-gather -> 160->80 -> 80->40 -> 40->1 --
#define PF_CH (128 * 36)
#define PF_SMEM_BYTES (5 * PF_CH * 4)   // 92160

__global__ __launch_bounds__(128)
void pred_fused(const float* __restrict__ h3,
                const float* __restrict__ P1t, const float* __restrict__ pb1,
                const float* __restrict__ P2t, const float* __restrict__ pb2,
                const float* __restrict__ P3,  const float* __restrict__ pb3,
                const int* __restrict__ ips, const int* __restrict__ ipd,
                const int* __restrict__ ins, const int* __restrict__ ind,
                float* __restrict__ out)
{
    extern __shared__ float smem[];
    float* sAd = smem;                 // [2][PF_CH]
    float* s1o = smem + 2 * PF_CH;     // [3][PF_CH]
    float* s2o = smem;                 // alias over sAd
    const uint32_t sAu = smem_u32(sAd);
    const uint32_t s1u = smem_u32(s1o);

    const int tid  = threadIdx.x;
    const int r0   = blockIdx.x * 128;
    const int lane = tid & 31;
    const int wq   = tid >> 5;
    const int wm   = wq & 1;
    const int wn   = wq >> 1;
    const int lr   = lane >> 2;
    const int lc   = lane & 3;
    const int sub  = lane >> 3;
    const int rr   = lane & 7;

    float4 rgA[8];
    auto fetchA = [&](int c) {
        const int k0 = c * 32;
        #pragma unroll
        for (int i = 0; i < 8; i++) {
            int idx = i * 128 + tid;
            int r = idx >> 3, kk = (idx & 7) * 4;
            int gm = r0 + r;
            int ia, ib;
            if (gm < NPAIRS) { ia = ips[gm]; ib = ipd[gm]; }
            else             { ia = ins[gm - NPAIRS]; ib = ind[gm - NPAIRS]; }
            float4 va = *(const float4*)(h3 + (size_t)ia * H3DIM + k0 + kk);
            float4 vb = *(const float4*)(h3 + (size_t)ib * H3DIM + k0 + kk);
            rgA[i] = make_float4(va.x*vb.x, va.y*vb.y, va.z*vb.z, va.w*vb.w);
        }
    };
    auto storeA = [&](int b) {
        #pragma unroll
        for (int i = 0; i < 8; i++) {
            int idx = i * 128 + tid;
            int r = idx >> 3, kk = (idx & 7) * 4;
            float4 v = rgA[i];
            v.x = tf32r(v.x); v.y = tf32r(v.y); v.z = tf32r(v.z); v.w = tf32r(v.w);
            *(float4*)(sAd + b * PF_CH + r * 36 + kk) = v;
        }
    };

    float a1[4][5][4];
    #pragma unroll
    for (int mt = 0; mt < 4; mt++)
        #pragma unroll
        for (int nt = 0; nt < 5; nt++)
            #pragma unroll
            for (int r = 0; r < 4; r++) a1[mt][nt][r] = 0.0f;

    auto compute1 = [&](int b, int c) {
        const uint32_t baseA = sAu + (uint32_t)b * (PF_CH * 4);
        #pragma unroll
        for (int ks = 0; ks < 4; ks++) {
            const int kb = ks * 8;
            const int kg = c * 32 + kb;
            uint32_t af[4][4], bf[5][2];
            #pragma unroll
            for (int mt = 0; mt < 4; mt++) {
                int row = wm * 64 + mt * 16 + rr + (sub & 1) * 8;
                int col = kb + (sub >> 1) * 4;
                uint32_t ad = baseA + (uint32_t)(row * 36 + col) * 4;
                asm volatile("ldmatrix.sync.aligned.m8n8.x4.shared.b16 {%0,%1,%2,%3}, [%4];"
                             : "=r"(af[mt][0]), "=r"(af[mt][1]), "=r"(af[mt][2]), "=r"(af[mt][3])
                             : "r"(ad));
            }
            #pragma unroll
            for (int nt = 0; nt < 5; nt++) {
                int n = wn * 40 + nt * 8 + lr;
                const float* bp = P1t + n * 160 + kg + lc;
                bf[nt][0] = __float_as_uint(__ldg(bp));
                bf[nt][1] = __float_as_uint(__ldg(bp + 4));
            }
            #pragma unroll
            for (int mt = 0; mt < 4; mt++)
                #pragma unroll
                for (int nt = 0; nt < 5; nt++)
                    asm volatile(
                        "mma.sync.aligned.m16n8k8.row.col.f32.tf32.tf32.f32 "
                        "{%0,%1,%2,%3}, {%4,%5,%6,%7}, {%8,%9}, {%0,%1,%2,%3};"
                        : "+f"(a1[mt][nt][0]), "+f"(a1[mt][nt][1]),
                          "+f"(a1[mt][nt][2]), "+f"(a1[mt][nt][3])
                        : "r"(af[mt][0]), "r"(af[mt][1]), "r"(af[mt][2]), "r"(af[mt][3]),
                          "r"(bf[nt][0]), "r"(bf[nt][1]));
        }
    };

    fetchA(0);
    storeA(0);
    for (int c = 0; c < 5; c++) {
        __syncthreads();
        if (c + 1 < 5) fetchA(c + 1);
        compute1(c & 1, c);
        if (c + 1 < 5) {
            __syncthreads();
            storeA((c + 1) & 1);
        }
    }

    #pragma unroll
    for (int mt = 0; mt < 4; mt++) {
        int row0 = wm * 64 + mt * 16 + lr;
        #pragma unroll
        for (int nt = 0; nt < 5; nt++) {
            int col = wn * 40 + nt * 8 + lc * 2;
            float bx = pb1[col], by = pb1[col + 1];
            int ch = col >> 5, ci = col & 31;
            #pragma unroll
            for (int half = 0; half < 2; half++) {
                int row = row0 + half * 8;
                float vx = a1[mt][nt][half * 2 + 0] + bx;
                float vy = a1[mt][nt][half * 2 + 1] + by;
                vx = (vx > 0.f) ? vx : 0.2f * vx;
                vy = (vy > 0.f) ? vy : 0.2f * vy;
                vx = tf32r(vx); vy = tf32r(vy);
                *(float2*)(s1o + ch * PF_CH + row * 36 + ci) = make_float2(vx, vy);
            }
        }
    }
    __syncthreads();

    float a2[2][5][4];
    #pragma unroll
    for (int mt = 0; mt < 2; mt++)
        #pragma unroll
        for (int nt = 0; nt < 5; nt++)
            #pragma unroll
            for (int r = 0; r < 4; r++) a2[mt][nt][r] = 0.0f;

    #pragma unroll
    for (int ch = 0; ch < 3; ch++) {
        const int nks = (ch < 2) ? 4 : 2;
        const uint32_t baseA = s1u + (uint32_t)ch * (PF_CH * 4);
        for (int ks = 0; ks < nks; ks++) {
            const int kb = ks * 8;
            const int kg = ch * 32 + kb;
            uint32_t af[2][4], bf[5][2];
            #pragma unroll
            for (int mt = 0; mt < 2; mt++) {
                int row = wq * 32 + mt * 16 + rr + (sub & 1) * 8;
                int col = kb + (sub >> 1) * 4;
                uint32_t ad = baseA + (uint32_t)(row * 36 + col) * 4;
                asm volatile("ldmatrix.sync.aligned.m8n8.x4.shared.b16 {%0,%1,%2,%3}, [%4];"
                             : "=r"(af[mt][0]), "=r"(af[mt][1]), "=r"(af[mt][2]), "=r"(af[mt][3])
                             : "r"(ad));
            }
            #pragma unroll
            for (int nt = 0; nt < 5; nt++) {
                int n = nt * 8 + lr;
                const float* bp = P2t + n * 80 + kg + lc;
                bf[nt][0] = __float_as_uint(__ldg(bp));
                bf[nt][1] = __float_as_uint(__ldg(bp + 4));
            }
            #pragma unroll
            for (int mt = 0; mt < 2; mt++)
                #pragma unroll
                for (int nt = 0; nt < 5; nt++)
                    asm volatile(
                        "mma.sync.aligned.m16n8k8.row.col.f32.tf32.tf32.f32 "
                        "{%0,%1,%2,%3}, {%4,%5,%6,%7}, {%8,%9}, {%0,%1,%2,%3};"
                        : "+f"(a2[mt][nt][0]), "+f"(a2[mt][nt][1]),
                          "+f"(a2[mt][nt][2]), "+f"(a2[mt][nt][3])
                        : "r"(af[mt][0]), "r"(af[mt][1]), "r"(af[mt][2]), "r"(af[mt][3]),
                          "r"(bf[nt][0]), "r"(bf[nt][1]));
        }
    }

    #pragma unroll
    for (int mt = 0; mt < 2; mt++) {
        int row0 = wq * 32 + mt * 16 + lr;
        #pragma unroll
        for (int nt = 0; nt < 5; nt++) {
            int col = nt * 8 + lc * 2;
            float bx = pb2[col], by = pb2[col + 1];
            #pragma unroll
            for (int half = 0; half < 2; half++) {
                int row = row0 + half * 8;
                float vx = a2[mt][nt][half * 2 + 0] + bx;
                float vy = a2[mt][nt][half * 2 + 1] + by;
                vx = (vx > 0.f) ? vx : 0.2f * vx;
                vy = (vy > 0.f) ? vy : 0.2f * vy;
                *(float2*)(s2o + row * 44 + col) = make_float2(vx, vy);
            }
        }
    }
    __syncthreads();

    float acc = __ldg(pb3);
    const float* rowp = s2o + tid * 44;
    #pragma unroll
    for (int k = 0; k < 40; k += 4) {
        float4 v = *(const float4*)(rowp + k);
        acc += v.x * __ldg(P3 + k + 0) + v.y * __ldg(P3 + k + 1)
             + v.z * __ldg(P3 + k + 2) + v.w * __ldg(P3 + k + 3);
    }
    out[r0 + tid] = acc;
}

// ---------------- launch ------------------------------------------------------
static inline dim3 mm_grid(int M, int Nn, int nt) { return dim3((Nn + nt - 1) / nt, (M + 127) / 128); }

extern "C" void kernel_launch(void* const* d_in, const int* in_sizes, int n_in,
                              void* d_out, int out_size)
{
    const float* x   = (const float*)d_in[0];
    const float* w   = (const float*)d_in[1];
    const int* src   = (const int*)d_in[2];
    const int* dst   = (const int*)d_in[3];
    const int* psrc  = (const int*)d_in[4];
    const int* pdst  = (const int*)d_in[5];
    const int* nsrc  = (const int*)d_in[6];
    const int* ndst  = (const int*)d_in[7];
    const float* W1  = (const float*)d_in[8];
    const float* b1  = (const float*)d_in[9];
    const float* W2  = (const float*)d_in[10];
    const float* b2  = (const float*)d_in[11];
    const float* W3  = (const float*)d_in[12];
    const float* b3  = (const float*)d_in[13];
    const float* P1  = (const float*)d_in[14];
    const float* pb1 = (const float*)d_in[15];
    const float* P2  = (const float*)d_in[16];
    const float* pb2 = (const float*)d_in[17];
    const float* P3  = (const float*)d_in[18];
    const float* pb3 = (const float*)d_in[19];

    float* out = (float*)d_out;
    float* out_h = out + NROWS_PAIR;   // [NPAIR pos | NPAIR neg | N*160 h]

    void *p_cntout, *p_cntin, *p_inorm;
    void *p_bufA, *p_bufB, *p_bufC, *p_Wt;
    cudaGetSymbolAddress(&p_cntout, g_cnt_out);
    cudaGetSymbolAddress(&p_cntin,  g_cnt_in);
    cudaGetSymbolAddress(&p_inorm,  g_inorm);
    cudaGetSymbolAddress(&p_bufA,   g_bufA);
    cudaGetSymbolAddress(&p_bufB,   g_bufB);
    cudaGetSymbolAddress(&p_bufC,   g_bufC);
    cudaGetSymbolAddress(&p_Wt,     g_Wt);
    float* inorm = (float*)p_inorm;
    float* bufA = (float*)p_bufA;
    float* bufB = (float*)p_bufB;
    float* bufC = (float*)p_bufC;
    float* W1t = (float*)p_Wt;
    float* W2t = W1t + 512 * 256;
    float* W3t = W2t + 256 * 512;
    float* P1t = W3t + 160 * 256;
    float* P2t = P1t + 80 * 160;

    cudaFuncSetAttribute(mm_gemm<1,1,1,128>, cudaFuncAttributeMaxDynamicSharedMemorySize, MM_SMEM(128));
    cudaFuncSetAttribute(mm_gemm<0,0,0,128>, cudaFuncAttributeMaxDynamicSharedMemorySize, MM_SMEM(128));
    cudaFuncSetAttribute(mm_gemm<0,0,0,64>,  cudaFuncAttributeMaxDynamicSharedMemorySize, MM_SMEM(64));
    cudaFuncSetAttribute(pred_fused, cudaFuncAttributeMaxDynamicSharedMemorySize, PF_SMEM_BYTES);

    const int E = NEDGES;

    // ---- graph preprocessing: counts -> (norms + scan) -> fill
    cudaMemsetAsync(p_cntout, 0, NNODES * sizeof(int));
    cudaMemsetAsync(p_cntin,  0, NNODES * sizeof(int));
    count_kernel<<<(E + 255) / 256, 256>>>(src, dst, E);
    scan_phase1<<<SCAN_BLOCKS, 256>>>();
    scan_phase2<<<1, 256>>>();
    scan_phase3<<<SCAN_BLOCKS, 256>>>();
    fill_kernel<<<(E + 255) / 256, 256>>>(src, dst, w, E);

    // single merged weight transpose (tf32-rounded)
    transpose_all<<<(TP2 + 255) / 256, 256>>>(W1, W2, W3, P1, P2, (float*)p_Wt);

    const int agg_blocks = (NNODES * 32 + 255) / 256;

    // ---- layer 1: agg(x) [round] -> GEMM1: @W1, *inorm+b1, relu, round
    csr_agg_kernel<DIN, 0><<<agg_blocks, 256>>>(x, bufA, nullptr);
    mm_gemm<1,1,1,128><<<mm_grid(NNODES, H1DIM, 128), 128, MM_SMEM(128)>>>(
        bufA, W1t, bufB, NNODES, DIN, H1DIM, inorm, b1);

    // ---- layer 2: GEMM2: h1@W2 -> agg2 with fused relu(*inorm+b2)+round
    mm_gemm<0,0,0,128><<<mm_grid(NNODES, H2DIM, 128), 128, MM_SMEM(128)>>>(
        bufB, W2t, bufA, NNODES, H1DIM, H2DIM, nullptr, nullptr);
    csr_agg_kernel<H2DIM, 1><<<agg_blocks, 256>>>(bufA, bufC, b2);

    // ---- layer 3: GEMM3 (NT=64, Nn=160): bufC@W3 -> agg3 fused *inorm+b3 -> out_h
    mm_gemm<0,0,0,64><<<mm_grid(NNODES, H3DIM, 64), 128, MM_SMEM(64)>>>(
        bufC, W3t, bufB, NNODES, H2DIM, H3DIM, nullptr, nullptr);
    csr_agg_kernel<H3DIM, 2><<<agg_blocks, 256>>>(bufB, out_h, b3);

    // ---- fused predictor: one launch for P1/P2/P3
    pred_fused<<<NROWS_PAIR / 128, 128, PF_SMEM_BYTES>>>(
        out_h, P1t, pb1, P2t, pb2, P3, pb3, psrc, pdst, nsrc, ndst, out);
}